// round 8
// baseline (speedup 1.0000x reference)
#include <cuda_runtime.h>
#include <cuda_bf16.h>
#include <math.h>
#include <stdint.h>

// Problem constants
#define B_  64
#define I_  320
#define H_  1536
#define L_  3
#define O_  256
#define H3_ 4608

#define GH_SPLIT 2
#define GI_SPLIT 6
#define I2H_SPLIT 5
#define H2O_SPLIT 24

#define KC 32            // fp32 k elements per chunk (128B row)
#define TM 128           // weight rows per block (MMA M side)
#define STAGE_SZ 24576   // W 128x128B (16KB) + Act 64x128B (8KB)
#define SM_TOTAL (2 * STAGE_SZ)

// Device scratch (static, no allocation)
__device__ __align__(16) float g_gh[GH_SPLIT * L_ * H3_ * B_];   // [l][p][j][b]
__device__ __align__(16) float g_gi_part[GI_SPLIT * H3_ * B_];   // [p][j][b]
__device__ __align__(16) float g_inp[B_ * H_];                   // [b][h]
__device__ __align__(16) float g_out_part[H2O_SPLIT * O_ * B_];  // [p][o][b]

__device__ __forceinline__ uint32_t smem_u32(const void* p) {
    uint32_t a;
    asm("{ .reg .u64 t; cvta.to.shared.u64 t, %1; cvt.u32.u64 %0, t; }" : "=r"(a) : "l"(p));
    return a;
}

#define LDM_X4(r, addr)                                                          \
    asm volatile("ldmatrix.sync.aligned.m8n8.x4.shared.b16 {%0,%1,%2,%3}, [%4];" \
                 : "=r"((r)[0]), "=r"((r)[1]), "=r"((r)[2]), "=r"((r)[3])        \
                 : "r"(addr))

#define MMA_TF32(c, a, b0, b1)                                                   \
    asm volatile("mma.sync.aligned.m16n8k8.row.col.f32.tf32.tf32.f32 "           \
                 "{%0,%1,%2,%3}, {%4,%5,%6,%7}, {%8,%9}, {%0,%1,%2,%3};"         \
                 : "+f"((c)[0]), "+f"((c)[1]), "+f"((c)[2]), "+f"((c)[3])        \
                 : "r"((a)[0]), "r"((a)[1]), "r"((a)[2]), "r"((a)[3]),           \
                   "r"(b0), "r"(b1))

__device__ __forceinline__ uint32_t to_tf32(float x) {
    uint32_t y;
    asm("cvt.rna.tf32.f32 %0, %1;" : "=r"(y) : "f"(x));
    return y;
}

// ---------------------------------------------------------------------------
// Cpart[z][y][j][b] = sum_{k in chunk} W[j][k] * Act[b][k]  (single-pass tf32)
// LDG.128 -> regs -> (cvt tf32) -> STS.128, 2-stage smem pipeline.
// Block tile 128(j) x 64(b); 8 warps of 32x32.
// ---------------------------------------------------------------------------
__global__ __launch_bounds__(256, 2)
void gemm_tc_kernel(const float* __restrict__ Act,
                    const float* __restrict__ W,
                    float* __restrict__ Cpart,
                    int N, int K, int kChunk,
                    long aBatchStride, long wBatchStride, long cBatchStride)
{
    extern __shared__ __align__(16) unsigned char smem[];
    const uint32_t smemB = smem_u32(smem);

    const int tid  = threadIdx.x;
    const int wid  = tid >> 5;
    const int lane = tid & 31;
    const int j0    = blockIdx.x * TM;
    const int kBase = blockIdx.y * kChunk;
    const int nChunks = kChunk >> 5;

    Act += (long)blockIdx.z * aBatchStride;
    W   += (long)blockIdx.z * wBatchStride;
    Cpart += (long)blockIdx.z * cBatchStride + (long)blockIdx.y * (long)N * B_;

    // ---- loader mapping ----
    const int wRow = tid >> 1;           // W row 0..127
    const int wG0  = (tid & 1) * 4;      // 16B-group base (4 of 8)
    const int aRow = tid >> 2;           // Act row 0..63
    const int aG0  = (tid & 3) * 2;      // 16B-group base (2 of 8)
    const float* wSrc = W + (long)(j0 + wRow) * K + kBase;
    const float* aSrc = Act + (long)aRow * K + kBase;
    const uint32_t wDstRow = wRow * 128;
    const uint32_t aDstRow = 16384 + aRow * 128;
    const int wSw = wRow & 7, aSw = aRow & 7;

    // ---- mma mapping: 8 warps = 4(M) x 2(N); warp tile 32x32 ----
    const int wm = wid & 3, wn = wid >> 2;
    const int r7 = lane & 7;
    const int aKhi = lane >> 4;
    const int bKhi = (lane >> 3) & 1;
    const int bNoff = (lane & 7) + ((lane >> 4) << 3);
    const uint32_t aOff0 = (uint32_t)(wm * 32 + (lane & 15)) * 128;
    const uint32_t aOff1 = aOff0 + 2048;
    const uint32_t bOff0 = 16384 + (uint32_t)(wn * 32 + bNoff) * 128;
    const uint32_t bOff1 = bOff0 + 2048;

    float acc[2][4][4];
#pragma unroll
    for (int mt = 0; mt < 2; mt++)
#pragma unroll
        for (int nt = 0; nt < 4; nt++)
#pragma unroll
            for (int q = 0; q < 4; q++) acc[mt][nt][q] = 0.0f;

    float4 wv[4], av[2];   // register staging for one chunk

    // LDG a chunk into registers
    auto ldg_chunk = [&](int c) {
        const float* ws = wSrc + c * KC;
#pragma unroll
        for (int g = 0; g < 4; g++)
            wv[g] = *reinterpret_cast<const float4*>(ws + (wG0 + g) * 4);
        const float* as = aSrc + c * KC;
#pragma unroll
        for (int g = 0; g < 2; g++)
            av[g] = *reinterpret_cast<const float4*>(as + (aG0 + g) * 4);
    };
    // cvt to tf32 + STS into stage
    auto sts_chunk = [&](int stage) {
        unsigned char* sb = smem + stage * STAGE_SZ;
#pragma unroll
        for (int g = 0; g < 4; g++) {
            uint4 t = make_uint4(to_tf32(wv[g].x), to_tf32(wv[g].y),
                                 to_tf32(wv[g].z), to_tf32(wv[g].w));
            *reinterpret_cast<uint4*>(sb + wDstRow + (((wG0 + g) ^ wSw) << 4)) = t;
        }
#pragma unroll
        for (int g = 0; g < 2; g++) {
            uint4 t = make_uint4(to_tf32(av[g].x), to_tf32(av[g].y),
                                 to_tf32(av[g].z), to_tf32(av[g].w));
            *reinterpret_cast<uint4*>(sb + aDstRow + (((aG0 + g) ^ aSw) << 4)) = t;
        }
    };

    // ---- prologue: chunk 0 staged; chunk 1 in flight ----
    ldg_chunk(0);
    sts_chunk(0);
    if (nChunks > 1) ldg_chunk(1);
    __syncthreads();

    for (int c = 0; c < nChunks; ++c) {
        // stage chunk c+1 (regs -> smem), then issue LDG for c+2
        if (c + 1 < nChunks) {
            sts_chunk((c + 1) & 1);
            if (c + 2 < nChunks) ldg_chunk(c + 2);
        }

        // ---- MMA on stage c&1: 4 k8 steps (no cvt — data already tf32) ----
        const uint32_t sb = smemB + (uint32_t)(c & 1) * STAGE_SZ;
#pragma unroll
        for (int s = 0; s < 4; s++) {
            uint32_t aF[2][4], bF[2][4];
            const uint32_t ga = (uint32_t)(((2 * s + aKhi) ^ r7) << 4);
            LDM_X4(aF[0], sb + aOff0 + ga);
            LDM_X4(aF[1], sb + aOff1 + ga);
            const uint32_t gb = (uint32_t)(((2 * s + bKhi) ^ r7) << 4);
            LDM_X4(bF[0], sb + bOff0 + gb);
            LDM_X4(bF[1], sb + bOff1 + gb);
#pragma unroll
            for (int mt = 0; mt < 2; mt++)
#pragma unroll
                for (int nt = 0; nt < 4; nt++) {
                    const int pr = nt >> 1, hf = (nt & 1) * 2;
                    MMA_TF32(acc[mt][nt], aF[mt], bF[pr][hf], bF[pr][hf + 1]);
                }
        }
        __syncthreads();
    }

    // ---- epilogue: write partial sums, layout [j][b] ----
#pragma unroll
    for (int mt = 0; mt < 2; mt++)
#pragma unroll
        for (int nt = 0; nt < 4; nt++) {
            const int j = j0 + wm * 32 + mt * 16 + (lane >> 2);
            const int b = wn * 32 + nt * 8 + (lane & 3) * 2;
            *reinterpret_cast<float2*>(&Cpart[(long)j * B_ + b]) =
                make_float2(acc[mt][nt][0], acc[mt][nt][1]);
            *reinterpret_cast<float2*>(&Cpart[(long)(j + 8) * B_ + b]) =
                make_float2(acc[mt][nt][2], acc[mt][nt][3]);
        }
}

// ---------------------------------------------------------------------------
// out[b][j] = bias[j] + sum_p parts[p][j][b]   (transposing combine)
// ---------------------------------------------------------------------------
__global__ void combine_t_kernel(const float* __restrict__ parts, int nsplit,
                                 const float* __restrict__ bias,
                                 float* __restrict__ out, int N)
{
    int idx = blockIdx.x * 256 + threadIdx.x;
    if (idx >= N * B_) return;
    int j = idx >> 6;
    int b = idx & 63;
    float s = bias[j];
    for (int p = 0; p < nsplit; p++) s += parts[(long)p * N * B_ + idx];
    out[(long)b * N + j] = s;
}

// ---------------------------------------------------------------------------
// GRU gate fusion; gi/gh partials in [p][j(4608)][b] layout.
// ---------------------------------------------------------------------------
__global__ void gru_gate_kernel(const float* __restrict__ giParts,
                                const float* __restrict__ ghParts,
                                const float* __restrict__ b_ih,
                                const float* __restrict__ b_hh,
                                const float* __restrict__ h_prev,   // [b][h]
                                float* __restrict__ h_out)          // [b][h]
{
    int idx = blockIdx.x * 256 + threadIdx.x;
    if (idx >= B_ * H_) return;
    int j = idx >> 6;
    int b = idx & 63;

    float gir = b_ih[j], giz = b_ih[H_ + j], gin = b_ih[2 * H_ + j];
#pragma unroll
    for (int p = 0; p < GI_SPLIT; p++) {
        const float* P = giParts + (long)p * H3_ * B_;
        gir += P[(long)j * B_ + b];
        giz += P[(long)(H_ + j) * B_ + b];
        gin += P[(long)(2 * H_ + j) * B_ + b];
    }
    float ghr = b_hh[j], ghz = b_hh[H_ + j], ghn = b_hh[2 * H_ + j];
#pragma unroll
    for (int p = 0; p < GH_SPLIT; p++) {
        const float* P = ghParts + (long)p * H3_ * B_;
        ghr += P[(long)j * B_ + b];
        ghz += P[(long)(H_ + j) * B_ + b];
        ghn += P[(long)(2 * H_ + j) * B_ + b];
    }

    float r = 1.0f / (1.0f + expf(-(gir + ghr)));
    float z = 1.0f / (1.0f + expf(-(giz + ghz)));
    float n = tanhf(gin + r * ghn);
    float hp = h_prev[(long)b * H_ + j];
    h_out[(long)b * H_ + j] = (1.0f - z) * n + z * hp;
}

// ---------------------------------------------------------------------------
extern "C" void kernel_launch(void* const* d_in, const int* in_sizes, int n_in,
                              void* d_out, int out_size)
{
    const float* x      = (const float*)d_in[0];   // [64,320]
    const float* hidden = (const float*)d_in[1];   // [3,64,1536]
    const float* w_i2h  = (const float*)d_in[2];   // [1536,320]
    const float* b_i2h  = (const float*)d_in[3];   // [1536]
    const float* w_ih   = (const float*)d_in[4];   // [3,4608,1536]
    const float* w_hh   = (const float*)d_in[5];   // [3,4608,1536]
    const float* b_ih   = (const float*)d_in[6];   // [3,4608]
    const float* b_hh   = (const float*)d_in[7];   // [3,4608]
    const float* w_h2o  = (const float*)d_in[8];   // [256,1536]
    const float* b_h2o  = (const float*)d_in[9];   // [256]
    (void)in_sizes; (void)n_in; (void)out_size;

    float* out     = (float*)d_out;                // [64,256]
    float* hid_out = (float*)d_out + B_ * O_;      // [3,64,1536]

    float *gh_ptr, *gi_ptr, *inp_ptr, *outp_ptr;
    cudaGetSymbolAddress((void**)&gh_ptr,   g_gh);
    cudaGetSymbolAddress((void**)&gi_ptr,   g_gi_part);
    cudaGetSymbolAddress((void**)&inp_ptr,  g_inp);
    cudaGetSymbolAddress((void**)&outp_ptr, g_out_part);

    cudaFuncSetAttribute(gemm_tc_kernel, cudaFuncAttributeMaxDynamicSharedMemorySize, SM_TOTAL);

    const long wLayerStride = (long)H3_ * H_;
    const long hLayerStride = (long)B_ * H_;
    const long ghLayerStride = (long)GH_SPLIT * H3_ * B_;

    // 1) gh, all 3 layers, split-K=2: grid (36, 2, 3), 24-chunk pipeline
    gemm_tc_kernel<<<dim3(H3_ / TM, GH_SPLIT, L_), 256, SM_TOTAL>>>(
        hidden, w_hh, gh_ptr, H3_, H_, H_ / GH_SPLIT,
        hLayerStride, wLayerStride, ghLayerStride);

    // 2) i2h: split-K=5: grid (12, 5), 2 chunks each
    gemm_tc_kernel<<<dim3(H_ / TM, I2H_SPLIT, 1), 256, SM_TOTAL>>>(
        x, w_i2h, gi_ptr, H_, I_, I_ / I2H_SPLIT, 0, 0, 0);
    combine_t_kernel<<<(H_ * B_ + 255) / 256, 256>>>(gi_ptr, I2H_SPLIT, b_i2h, inp_ptr, H_);

    // 3) layer chain: gi split-K=6 -> grid (36, 6) = 216 blocks, 8 chunks each
    const float* inp = inp_ptr;
    for (int l = 0; l < L_; l++) {
        gemm_tc_kernel<<<dim3(H3_ / TM, GI_SPLIT, 1), 256, SM_TOTAL>>>(
            inp, w_ih + (long)l * wLayerStride, gi_ptr,
            H3_, H_, H_ / GI_SPLIT, 0, 0, 0);
        gru_gate_kernel<<<(B_ * H_ + 255) / 256, 256>>>(
            gi_ptr, gh_ptr + (long)l * ghLayerStride,
            b_ih + (long)l * H3_, b_hh + (long)l * H3_,
            hidden + (long)l * hLayerStride,
            hid_out + (long)l * hLayerStride);
        inp = hid_out + (long)l * hLayerStride;
    }

    // 4) h2o: grid (2, 24), 2 chunks each
    gemm_tc_kernel<<<dim3(O_ / TM, H2O_SPLIT, 1), 256, SM_TOTAL>>>(
        inp, w_h2o, outp_ptr, O_, H_, H_ / H2O_SPLIT, 0, 0, 0);
    combine_t_kernel<<<(O_ * B_ + 255) / 256, 256>>>(outp_ptr, H2O_SPLIT, b_h2o, out, O_);
}

// round 9
// speedup vs baseline: 1.0324x; 1.0324x over previous
#include <cuda_runtime.h>
#include <cuda_bf16.h>
#include <math.h>
#include <stdint.h>

// Problem constants
#define B_  64
#define I_  320
#define H_  1536
#define L_  3
#define O_  256
#define H3_ 4608

#define GH_SPLIT 4
#define GI_SPLIT 4
#define I2H_SPLIT 5
#define H2O_SPLIT 24

#define TM 128           // weight rows per block (MMA M side)

// ---- bulk-DMA gemm config ----
#define BKC 128                  // fp32 k per big chunk (512B per row)
#define PITCH 528                // 512 + 16: odd multiple of 16B -> conflict-free ldmatrix
#define SM_A_OFF (128 * PITCH)   // Act tile after W tile (67584)
#define BSTAGE (192 * PITCH)     // 101376 bytes per stage
#define SM_MBAR_OFF (2 * BSTAGE) // 202752
#define BULK_SMEM (SM_MBAR_OFF + 64)
#define STAGE_BYTES (192 * 512)  // expect_tx bytes: 98304

// ---- cp.async gemm config (small GEMMs) ----
#define KC 32
#define STAGE_SZ 24576
#define SM_TOTAL (4 * STAGE_SZ)

// Device scratch (static, no allocation)
__device__ __align__(16) float g_gh[GH_SPLIT * L_ * H3_ * B_];   // [l][p][j][b]
__device__ __align__(16) float g_gi_part[GI_SPLIT * H3_ * B_];   // [p][j][b]
__device__ __align__(16) float g_inp[B_ * H_];                   // [b][h]
__device__ __align__(16) float g_out_part[H2O_SPLIT * O_ * B_];  // [p][o][b]

__device__ __forceinline__ uint32_t smem_u32(const void* p) {
    uint32_t a;
    asm("{ .reg .u64 t; cvta.to.shared.u64 t, %1; cvt.u32.u64 %0, t; }" : "=r"(a) : "l"(p));
    return a;
}

#define CP_ASYNC16(dst, src) \
    asm volatile("cp.async.cg.shared.global [%0], [%1], 16;" :: "r"(dst), "l"(src) : "memory")
#define CP_COMMIT() asm volatile("cp.async.commit_group;" ::: "memory")
#define CP_WAIT2()  asm volatile("cp.async.wait_group 2;" ::: "memory")

#define BULK_LD(dst, src, bytes, mbar)                                            \
    asm volatile("cp.async.bulk.shared::cta.global.mbarrier::complete_tx::bytes " \
                 "[%0], [%1], %2, [%3];"                                          \
                 :: "r"(dst), "l"(src), "r"(bytes), "r"(mbar) : "memory")

#define MBAR_INIT(mbar, cnt) \
    asm volatile("mbarrier.init.shared.b64 [%0], %1;" :: "r"(mbar), "r"(cnt) : "memory")
#define MBAR_EXPECT(mbar, bytes) \
    asm volatile("mbarrier.arrive.expect_tx.shared.b64 _, [%0], %1;" :: "r"(mbar), "r"(bytes) : "memory")

__device__ __forceinline__ void mbar_wait(uint32_t mbar, uint32_t parity) {
    asm volatile(
        "{\n\t.reg .pred P;\n\t"
        "WL_%=:\n\t"
        "mbarrier.try_wait.parity.acquire.cta.shared::cta.b64 P, [%0], %1, 0x989680;\n\t"
        "@P bra.uni WD_%=;\n\t"
        "bra.uni WL_%=;\n\t"
        "WD_%=:\n\t}"
        :: "r"(mbar), "r"(parity) : "memory");
}

#define LDM_X4(r, addr)                                                          \
    asm volatile("ldmatrix.sync.aligned.m8n8.x4.shared.b16 {%0,%1,%2,%3}, [%4];" \
                 : "=r"((r)[0]), "=r"((r)[1]), "=r"((r)[2]), "=r"((r)[3])        \
                 : "r"(addr))

#define MMA_TF32(c, a, b0, b1)                                                   \
    asm volatile("mma.sync.aligned.m16n8k8.row.col.f32.tf32.tf32.f32 "           \
                 "{%0,%1,%2,%3}, {%4,%5,%6,%7}, {%8,%9}, {%0,%1,%2,%3};"         \
                 : "+f"((c)[0]), "+f"((c)[1]), "+f"((c)[2]), "+f"((c)[3])        \
                 : "r"((a)[0]), "r"((a)[1]), "r"((a)[2]), "r"((a)[3]),           \
                   "r"(b0), "r"(b1))

__device__ __forceinline__ uint32_t to_tf32_u(uint32_t x) {
    uint32_t y;
    asm("cvt.rna.tf32.f32 %0, %1;" : "=r"(y) : "f"(__uint_as_float(x)));
    return y;
}
__device__ __forceinline__ uint32_t to_tf32(float x) {
    uint32_t y;
    asm("cvt.rna.tf32.f32 %0, %1;" : "=r"(y) : "f"(x));
    return y;
}

// ---------------------------------------------------------------------------
// Bulk-DMA tf32 GEMM: Cpart[z][y][j][b] = sum_k W[j][k] * Act[b][k]
// K streamed in big chunks of 128 fp32 via cp.async.bulk (one 512B copy per
// row), double-buffered; padded pitch 528B keeps ldmatrix conflict-free.
// ---------------------------------------------------------------------------
__global__ __launch_bounds__(256, 1)
void gemm_bulk_kernel(const float* __restrict__ Act,
                      const float* __restrict__ W,
                      float* __restrict__ Cpart,
                      int N, int K, int kChunk,
                      long aBatchStride, long wBatchStride, long cBatchStride)
{
    extern __shared__ __align__(16) unsigned char smem[];
    const uint32_t smemB = smem_u32(smem);
    const uint32_t mbar = smemB + SM_MBAR_OFF;

    const int tid  = threadIdx.x;
    const int wid  = tid >> 5;
    const int lane = tid & 31;
    const int j0    = blockIdx.x * TM;
    const int kBase = blockIdx.y * kChunk;
    const int nBig  = kChunk / BKC;

    Act += (long)blockIdx.z * aBatchStride;
    W   += (long)blockIdx.z * wBatchStride;
    Cpart += (long)blockIdx.z * cBatchStride + (long)blockIdx.y * (long)N * B_;

    if (tid == 0) { MBAR_INIT(mbar, 1); MBAR_INIT(mbar + 8, 1); }
    __syncthreads();

    const float* wTile = W + (long)j0 * K + kBase;
    const float* aTile = Act + kBase;

    // warp 0 issues one stage's DMA (expect_tx + 6 bulk copies per lane)
    auto issue = [&](int c) {
        if (wid == 0) {
            const uint32_t mb = mbar + (uint32_t)(c & 1) * 8;
            if (lane == 0) MBAR_EXPECT(mb, STAGE_BYTES);
            __syncwarp();
            const uint32_t sb = smemB + (uint32_t)(c & 1) * BSTAGE;
            const float* wk = wTile + c * BKC;
            const float* ak = aTile + c * BKC;
#pragma unroll
            for (int q = 0; q < 4; q++) {
                const int r = lane + q * 32;
                BULK_LD(sb + r * PITCH, wk + (long)r * K, 512u, mb);
            }
#pragma unroll
            for (int q = 0; q < 2; q++) {
                const int r = lane + q * 32;
                BULK_LD(sb + SM_A_OFF + r * PITCH, ak + (long)r * K, 512u, mb);
            }
        }
    };

    // ---- mma mapping: 8 warps = 4(M) x 2(N); warp tile 32x32 ----
    const int wm = wid & 3, wn = wid >> 2;
    const int aKhi = lane >> 4;
    const int bKhi = (lane >> 3) & 1;
    const int bNoff = (lane & 7) + ((lane >> 4) << 3);
    const uint32_t aOff0 = (uint32_t)(wm * 32 + (lane & 15)) * PITCH;
    const uint32_t aOff1 = aOff0 + 16 * PITCH;
    const uint32_t bOff0 = SM_A_OFF + (uint32_t)(wn * 32 + bNoff) * PITCH;
    const uint32_t bOff1 = bOff0 + 16 * PITCH;

    float acc[2][4][4];
#pragma unroll
    for (int mt = 0; mt < 2; mt++)
#pragma unroll
        for (int nt = 0; nt < 4; nt++)
#pragma unroll
            for (int q = 0; q < 4; q++) acc[mt][nt][q] = 0.0f;

    issue(0);
    if (nBig > 1) issue(1);

    for (int c = 0; c < nBig; ++c) {
        mbar_wait(mbar + (uint32_t)(c & 1) * 8, (uint32_t)(c >> 1) & 1);

        const uint32_t sb = smemB + (uint32_t)(c & 1) * BSTAGE;
#pragma unroll
        for (int s = 0; s < 16; s++) {
            uint32_t aF[2][4], bF[2][4];
            const uint32_t ga = (uint32_t)((2 * s + aKhi) << 4);
            LDM_X4(aF[0], sb + aOff0 + ga);
            LDM_X4(aF[1], sb + aOff1 + ga);
            const uint32_t gb = (uint32_t)((2 * s + bKhi) << 4);
            LDM_X4(bF[0], sb + bOff0 + gb);
            LDM_X4(bF[1], sb + bOff1 + gb);
#pragma unroll
            for (int mt = 0; mt < 2; mt++)
#pragma unroll
                for (int q = 0; q < 4; q++) aF[mt][q] = to_tf32_u(aF[mt][q]);
#pragma unroll
            for (int pr = 0; pr < 2; pr++)
#pragma unroll
                for (int q = 0; q < 4; q++) bF[pr][q] = to_tf32_u(bF[pr][q]);
#pragma unroll
            for (int mt = 0; mt < 2; mt++)
#pragma unroll
                for (int nt = 0; nt < 4; nt++) {
                    const int pr = nt >> 1, hf = (nt & 1) * 2;
                    MMA_TF32(acc[mt][nt], aF[mt], bF[pr][hf], bF[pr][hf + 1]);
                }
        }

        __syncthreads();             // all warps done with this stage buffer
        if (c + 2 < nBig) issue(c + 2);
    }

    // ---- epilogue: write partial sums, layout [j][b] ----
#pragma unroll
    for (int mt = 0; mt < 2; mt++)
#pragma unroll
        for (int nt = 0; nt < 4; nt++) {
            const int j = j0 + wm * 32 + mt * 16 + (lane >> 2);
            const int b = wn * 32 + nt * 8 + (lane & 3) * 2;
            *reinterpret_cast<float2*>(&Cpart[(long)j * B_ + b]) =
                make_float2(acc[mt][nt][0], acc[mt][nt][1]);
            *reinterpret_cast<float2*>(&Cpart[(long)(j + 8) * B_ + b]) =
                make_float2(acc[mt][nt][2], acc[mt][nt][3]);
        }
}

// ---------------------------------------------------------------------------
// cp.async tf32 GEMM (R7 version) — used for the small i2h / h2o GEMMs.
// ---------------------------------------------------------------------------
__global__ __launch_bounds__(256, 2)
void gemm_tc_kernel(const float* __restrict__ Act,
                    const float* __restrict__ W,
                    float* __restrict__ Cpart,
                    int N, int K, int kChunk,
                    long aBatchStride, long wBatchStride, long cBatchStride)
{
    extern __shared__ __align__(16) unsigned char smem[];
    const uint32_t smemB = smem_u32(smem);

    const int tid  = threadIdx.x;
    const int wid  = tid >> 5;
    const int lane = tid & 31;
    const int j0    = blockIdx.x * TM;
    const int kBase = blockIdx.y * kChunk;
    const int nChunks = kChunk >> 5;

    Act += (long)blockIdx.z * aBatchStride;
    W   += (long)blockIdx.z * wBatchStride;
    Cpart += (long)blockIdx.z * cBatchStride + (long)blockIdx.y * (long)N * B_;

    const int wRow = tid >> 1;
    const int wG0  = (tid & 1) * 4;
    const int aRow = tid >> 2;
    const int aG0  = (tid & 3) * 2;
    const float* wSrc = W + (long)(j0 + wRow) * K + kBase;
    const float* aSrc = Act + (long)aRow * K + kBase;
    const uint32_t wDstRow = wRow * 128;
    const uint32_t aDstRow = 16384 + aRow * 128;
    const int wSw = wRow & 7, aSw = aRow & 7;

    const int wm = wid & 3, wn = wid >> 2;
    const int r7 = lane & 7;
    const int aKhi = lane >> 4;
    const int bKhi = (lane >> 3) & 1;
    const int bNoff = (lane & 7) + ((lane >> 4) << 3);
    const uint32_t aOff0 = (uint32_t)(wm * 32 + (lane & 15)) * 128;
    const uint32_t aOff1 = aOff0 + 2048;
    const uint32_t bOff0 = 16384 + (uint32_t)(wn * 32 + bNoff) * 128;
    const uint32_t bOff1 = bOff0 + 2048;

    float acc[2][4][4];
#pragma unroll
    for (int mt = 0; mt < 2; mt++)
#pragma unroll
        for (int nt = 0; nt < 4; nt++)
#pragma unroll
            for (int q = 0; q < 4; q++) acc[mt][nt][q] = 0.0f;

#pragma unroll
    for (int p = 0; p < 3; p++) {
        if (p < nChunks) {
            const uint32_t sb = smemB + (uint32_t)p * STAGE_SZ;
#pragma unroll
            for (int g = 0; g < 4; g++) {
                const int kg = wG0 + g;
                CP_ASYNC16(sb + wDstRow + ((kg ^ wSw) << 4), wSrc + p * KC + kg * 4);
            }
#pragma unroll
            for (int g = 0; g < 2; g++) {
                const int kg = aG0 + g;
                CP_ASYNC16(sb + aDstRow + ((kg ^ aSw) << 4), aSrc + p * KC + kg * 4);
            }
        }
        CP_COMMIT();
    }

    for (int c = 0; c < nChunks; ++c) {
        CP_WAIT2();
        __syncthreads();

        if (c + 3 < nChunks) {
            const uint32_t sb = smemB + (uint32_t)((c + 3) & 3) * STAGE_SZ;
#pragma unroll
            for (int g = 0; g < 4; g++) {
                const int kg = wG0 + g;
                CP_ASYNC16(sb + wDstRow + ((kg ^ wSw) << 4), wSrc + (c + 3) * KC + kg * 4);
            }
#pragma unroll
            for (int g = 0; g < 2; g++) {
                const int kg = aG0 + g;
                CP_ASYNC16(sb + aDstRow + ((kg ^ aSw) << 4), aSrc + (c + 3) * KC + kg * 4);
            }
        }
        CP_COMMIT();

        const uint32_t sb = smemB + (uint32_t)(c & 3) * STAGE_SZ;
#pragma unroll
        for (int s = 0; s < 4; s++) {
            uint32_t aF[2][4], bF[2][4];
            const uint32_t ga = (uint32_t)(((2 * s + aKhi) ^ r7) << 4);
            LDM_X4(aF[0], sb + aOff0 + ga);
            LDM_X4(aF[1], sb + aOff1 + ga);
            const uint32_t gb = (uint32_t)(((2 * s + bKhi) ^ r7) << 4);
            LDM_X4(bF[0], sb + bOff0 + gb);
            LDM_X4(bF[1], sb + bOff1 + gb);
#pragma unroll
            for (int mt = 0; mt < 2; mt++)
#pragma unroll
                for (int q = 0; q < 4; q++) aF[mt][q] = to_tf32_u(aF[mt][q]);
#pragma unroll
            for (int pr = 0; pr < 2; pr++)
#pragma unroll
                for (int q = 0; q < 4; q++) bF[pr][q] = to_tf32_u(bF[pr][q]);
#pragma unroll
            for (int mt = 0; mt < 2; mt++)
#pragma unroll
                for (int nt = 0; nt < 4; nt++) {
                    const int pr = nt >> 1, hf = (nt & 1) * 2;
                    MMA_TF32(acc[mt][nt], aF[mt], bF[pr][hf], bF[pr][hf + 1]);
                }
        }
    }

#pragma unroll
    for (int mt = 0; mt < 2; mt++)
#pragma unroll
        for (int nt = 0; nt < 4; nt++) {
            const int j = j0 + wm * 32 + mt * 16 + (lane >> 2);
            const int b = wn * 32 + nt * 8 + (lane & 3) * 2;
            *reinterpret_cast<float2*>(&Cpart[(long)j * B_ + b]) =
                make_float2(acc[mt][nt][0], acc[mt][nt][1]);
            *reinterpret_cast<float2*>(&Cpart[(long)(j + 8) * B_ + b]) =
                make_float2(acc[mt][nt][2], acc[mt][nt][3]);
        }
}

// ---------------------------------------------------------------------------
// out[b][j] = bias[j] + sum_p parts[p][j][b]   (transposing combine)
// ---------------------------------------------------------------------------
__global__ void combine_t_kernel(const float* __restrict__ parts, int nsplit,
                                 const float* __restrict__ bias,
                                 float* __restrict__ out, int N)
{
    int idx = blockIdx.x * 256 + threadIdx.x;
    if (idx >= N * B_) return;
    int j = idx >> 6;
    int b = idx & 63;
    float s = bias[j];
    for (int p = 0; p < nsplit; p++) s += parts[(long)p * N * B_ + idx];
    out[(long)b * N + j] = s;
}

// ---------------------------------------------------------------------------
// GRU gate fusion; gi/gh partials in [p][j(4608)][b] layout.
// ---------------------------------------------------------------------------
__global__ void gru_gate_kernel(const float* __restrict__ giParts,
                                const float* __restrict__ ghParts,
                                const float* __restrict__ b_ih,
                                const float* __restrict__ b_hh,
                                const float* __restrict__ h_prev,   // [b][h]
                                float* __restrict__ h_out)          // [b][h]
{
    int idx = blockIdx.x * 256 + threadIdx.x;
    if (idx >= B_ * H_) return;
    int j = idx >> 6;
    int b = idx & 63;

    float gir = b_ih[j], giz = b_ih[H_ + j], gin = b_ih[2 * H_ + j];
#pragma unroll
    for (int p = 0; p < GI_SPLIT; p++) {
        const float* P = giParts + (long)p * H3_ * B_;
        gir += P[(long)j * B_ + b];
        giz += P[(long)(H_ + j) * B_ + b];
        gin += P[(long)(2 * H_ + j) * B_ + b];
    }
    float ghr = b_hh[j], ghz = b_hh[H_ + j], ghn = b_hh[2 * H_ + j];
#pragma unroll
    for (int p = 0; p < GH_SPLIT; p++) {
        const float* P = ghParts + (long)p * H3_ * B_;
        ghr += P[(long)j * B_ + b];
        ghz += P[(long)(H_ + j) * B_ + b];
        ghn += P[(long)(2 * H_ + j) * B_ + b];
    }

    float r = 1.0f / (1.0f + expf(-(gir + ghr)));
    float z = 1.0f / (1.0f + expf(-(giz + ghz)));
    float n = tanhf(gin + r * ghn);
    float hp = h_prev[(long)b * H_ + j];
    h_out[(long)b * H_ + j] = (1.0f - z) * n + z * hp;
}

// ---------------------------------------------------------------------------
extern "C" void kernel_launch(void* const* d_in, const int* in_sizes, int n_in,
                              void* d_out, int out_size)
{
    const float* x      = (const float*)d_in[0];   // [64,320]
    const float* hidden = (const float*)d_in[1];   // [3,64,1536]
    const float* w_i2h  = (const float*)d_in[2];   // [1536,320]
    const float* b_i2h  = (const float*)d_in[3];   // [1536]
    const float* w_ih   = (const float*)d_in[4];   // [3,4608,1536]
    const float* w_hh   = (const float*)d_in[5];   // [3,4608,1536]
    const float* b_ih   = (const float*)d_in[6];   // [3,4608]
    const float* b_hh   = (const float*)d_in[7];   // [3,4608]
    const float* w_h2o  = (const float*)d_in[8];   // [256,1536]
    const float* b_h2o  = (const float*)d_in[9];   // [256]
    (void)in_sizes; (void)n_in; (void)out_size;

    float* out     = (float*)d_out;                // [64,256]
    float* hid_out = (float*)d_out + B_ * O_;      // [3,64,1536]

    float *gh_ptr, *gi_ptr, *inp_ptr, *outp_ptr;
    cudaGetSymbolAddress((void**)&gh_ptr,   g_gh);
    cudaGetSymbolAddress((void**)&gi_ptr,   g_gi_part);
    cudaGetSymbolAddress((void**)&inp_ptr,  g_inp);
    cudaGetSymbolAddress((void**)&outp_ptr, g_out_part);

    cudaFuncSetAttribute(gemm_bulk_kernel, cudaFuncAttributeMaxDynamicSharedMemorySize, BULK_SMEM);
    cudaFuncSetAttribute(gemm_tc_kernel,   cudaFuncAttributeMaxDynamicSharedMemorySize, SM_TOTAL);

    const long wLayerStride = (long)H3_ * H_;
    const long hLayerStride = (long)B_ * H_;
    const long ghLayerStride = (long)GH_SPLIT * H3_ * B_;

    // 1) gh, all 3 layers, split-K=4: grid (36, 4, 3) = 432 bulk CTAs, kChunk=384
    gemm_bulk_kernel<<<dim3(H3_ / TM, GH_SPLIT, L_), 256, BULK_SMEM>>>(
        hidden, w_hh, gh_ptr, H3_, H_, H_ / GH_SPLIT,
        hLayerStride, wLayerStride, ghLayerStride);

    // 2) i2h (small): cp.async kernel, split-K=5
    gemm_tc_kernel<<<dim3(H_ / TM, I2H_SPLIT, 1), 256, SM_TOTAL>>>(
        x, w_i2h, gi_ptr, H_, I_, I_ / I2H_SPLIT, 0, 0, 0);
    combine_t_kernel<<<(H_ * B_ + 255) / 256, 256>>>(gi_ptr, I2H_SPLIT, b_i2h, inp_ptr, H_);

    // 3) layer chain: gi split-K=4 -> grid (36, 4) = 144 bulk CTAs, kChunk=384
    const float* inp = inp_ptr;
    for (int l = 0; l < L_; l++) {
        gemm_bulk_kernel<<<dim3(H3_ / TM, GI_SPLIT, 1), 256, BULK_SMEM>>>(
            inp, w_ih + (long)l * wLayerStride, gi_ptr,
            H3_, H_, H_ / GI_SPLIT, 0, 0, 0);
        gru_gate_kernel<<<(B_ * H_ + 255) / 256, 256>>>(
            gi_ptr, gh_ptr + (long)l * ghLayerStride,
            b_ih + (long)l * H3_, b_hh + (long)l * H3_,
            hidden + (long)l * hLayerStride,
            hid_out + (long)l * hLayerStride);
        inp = hid_out + (long)l * hLayerStride;
    }

    // 4) h2o (small): cp.async kernel
    gemm_tc_kernel<<<dim3(O_ / TM, H2O_SPLIT, 1), 256, SM_TOTAL>>>(
        inp, w_h2o, outp_ptr, O_, H_, H_ / H2O_SPLIT, 0, 0, 0);
    combine_t_kernel<<<(O_ * B_ + 255) / 256, 256>>>(outp_ptr, H2O_SPLIT, b_h2o, out, O_);
}

// round 10
// speedup vs baseline: 1.3841x; 1.3406x over previous
#include <cuda_runtime.h>
#include <cuda_bf16.h>
#include <math.h>
#include <stdint.h>

// Problem constants
#define B_  64
#define I_  320
#define H_  1536
#define L_  3
#define O_  256
#define H3_ 4608

#define GH_SPLIT 4
#define GI_SPLIT 4
#define I2H_SPLIT 5
#define H2O_SPLIT 24

#define KC 64            // fp32 k elements per chunk (256B row)
#define TM 128           // weight rows per block (MMA M side)
#define STAGE_SZ 49152   // W 128x256B (32KB) + Act 64x256B (16KB)
#define SM_A_OFF 32768
#define SM_TOTAL (4 * STAGE_SZ)   // 196608

// Device scratch (static, no allocation)
__device__ __align__(16) float g_gh[GH_SPLIT * L_ * H3_ * B_];   // [l][p][j][b]
__device__ __align__(16) float g_gi_part[GI_SPLIT * H3_ * B_];   // [p][j][b]
__device__ __align__(16) float g_inp[B_ * H_];                   // [b][h]
__device__ __align__(16) float g_out_part[H2O_SPLIT * O_ * B_];  // [p][o][b]

__device__ __forceinline__ uint32_t smem_u32(const void* p) {
    uint32_t a;
    asm("{ .reg .u64 t; cvta.to.shared.u64 t, %1; cvt.u32.u64 %0, t; }" : "=r"(a) : "l"(p));
    return a;
}

#define CP_ASYNC16(dst, src) \
    asm volatile("cp.async.cg.shared.global [%0], [%1], 16;" :: "r"(dst), "l"(src) : "memory")
#define CP_COMMIT() asm volatile("cp.async.commit_group;" ::: "memory")
#define CP_WAIT2()  asm volatile("cp.async.wait_group 2;" ::: "memory")

#define LDM_X4(r, addr)                                                          \
    asm volatile("ldmatrix.sync.aligned.m8n8.x4.shared.b16 {%0,%1,%2,%3}, [%4];" \
                 : "=r"((r)[0]), "=r"((r)[1]), "=r"((r)[2]), "=r"((r)[3])        \
                 : "r"(addr))

#define MMA_TF32(c, a, b0, b1)                                                   \
    asm volatile("mma.sync.aligned.m16n8k8.row.col.f32.tf32.tf32.f32 "           \
                 "{%0,%1,%2,%3}, {%4,%5,%6,%7}, {%8,%9}, {%0,%1,%2,%3};"         \
                 : "+f"((c)[0]), "+f"((c)[1]), "+f"((c)[2]), "+f"((c)[3])        \
                 : "r"((a)[0]), "r"((a)[1]), "r"((a)[2]), "r"((a)[3]),           \
                   "r"(b0), "r"(b1))

__device__ __forceinline__ uint32_t to_tf32_u(uint32_t x) {
    uint32_t y;
    asm("cvt.rna.tf32.f32 %0, %1;" : "=r"(y) : "f"(__uint_as_float(x)));
    return y;
}

// ---------------------------------------------------------------------------
// Cpart[z][y][j][b] = sum_{k in chunk} W[j][k] * Act[b][k]  (single-pass tf32)
// cp.async 4-stage pipeline, KC=64 (256B rows), XOR-16 swizzle.
// Block tile 128(j) x 64(b); 8 warps of 32x32.
// ---------------------------------------------------------------------------
__global__ __launch_bounds__(256, 1)
void gemm_tc_kernel(const float* __restrict__ Act,
                    const float* __restrict__ W,
                    float* __restrict__ Cpart,
                    int N, int K, int kChunk,
                    long aBatchStride, long wBatchStride, long cBatchStride)
{
    extern __shared__ __align__(16) unsigned char smem[];
    const uint32_t smemB = smem_u32(smem);

    const int tid  = threadIdx.x;
    const int wid  = tid >> 5;
    const int lane = tid & 31;
    const int j0    = blockIdx.x * TM;
    const int kBase = blockIdx.y * kChunk;
    const int nChunks = kChunk >> 6;

    Act += (long)blockIdx.z * aBatchStride;
    W   += (long)blockIdx.z * wBatchStride;
    Cpart += (long)blockIdx.z * cBatchStride + (long)blockIdx.y * (long)N * B_;

    // ---- cp.async loader mapping (granule = 16B = 4 fp32) ----
    const int wRow = tid >> 1;            // W row 0..127
    const int wG0  = (tid & 1) * 8;       // 8 granules of 16
    const int aRow = tid >> 2;            // Act row 0..63
    const int aG0  = (tid & 3) * 4;       // 4 granules of 16
    const float* wSrc = W + (long)(j0 + wRow) * K + kBase;
    const float* aSrc = Act + (long)aRow * K + kBase;
    const uint32_t wDstRow = wRow * 256;
    const uint32_t aDstRow = SM_A_OFF + aRow * 256;
    const int wSw = wRow & 15, aSw = aRow & 15;

    // ---- mma mapping: 8 warps = 4(M) x 2(N); warp tile 32x32 ----
    const int wm = wid & 3, wn = wid >> 2;
    const int aKhi = lane >> 4;
    const int bKhi = (lane >> 3) & 1;
    const int bNoff = (lane & 7) + ((lane >> 4) << 3);
    const int aSwm = lane & 15;           // A-row swizzle key (row & 15)
    const int bSwm = bNoff;               // B-row swizzle key (row & 15)
    const uint32_t aOff0 = (uint32_t)(wm * 32 + (lane & 15)) * 256;
    const uint32_t aOff1 = aOff0 + 4096;
    const uint32_t bOff0 = SM_A_OFF + (uint32_t)(wn * 32 + bNoff) * 256;
    const uint32_t bOff1 = bOff0 + 4096;

    float acc[2][4][4];
#pragma unroll
    for (int mt = 0; mt < 2; mt++)
#pragma unroll
        for (int nt = 0; nt < 4; nt++)
#pragma unroll
            for (int q = 0; q < 4; q++) acc[mt][nt][q] = 0.0f;

    // ---- prologue: stages 0..2 ----
#pragma unroll
    for (int p = 0; p < 3; p++) {
        if (p < nChunks) {
            const uint32_t sb = smemB + (uint32_t)p * STAGE_SZ;
#pragma unroll
            for (int g = 0; g < 8; g++) {
                const int kg = wG0 + g;
                CP_ASYNC16(sb + wDstRow + ((kg ^ wSw) << 4), wSrc + p * KC + kg * 4);
            }
#pragma unroll
            for (int g = 0; g < 4; g++) {
                const int kg = aG0 + g;
                CP_ASYNC16(sb + aDstRow + ((kg ^ aSw) << 4), aSrc + p * KC + kg * 4);
            }
        }
        CP_COMMIT();
    }

    for (int c = 0; c < nChunks; ++c) {
        CP_WAIT2();
        __syncthreads();   // stage c visible; all warps done with stage c-2's buffer

        // issue stage c+3 (overlaps with MMA below)
        if (c + 3 < nChunks) {
            const uint32_t sb = smemB + (uint32_t)((c + 3) & 3) * STAGE_SZ;
#pragma unroll
            for (int g = 0; g < 8; g++) {
                const int kg = wG0 + g;
                CP_ASYNC16(sb + wDstRow + ((kg ^ wSw) << 4), wSrc + (c + 3) * KC + kg * 4);
            }
#pragma unroll
            for (int g = 0; g < 4; g++) {
                const int kg = aG0 + g;
                CP_ASYNC16(sb + aDstRow + ((kg ^ aSw) << 4), aSrc + (c + 3) * KC + kg * 4);
            }
        }
        CP_COMMIT();

        // ---- MMA on stage c&3: 8 k8 steps ----
        const uint32_t sb = smemB + (uint32_t)(c & 3) * STAGE_SZ;
#pragma unroll
        for (int s = 0; s < 8; s++) {
            uint32_t aF[2][4], bF[2][4];
            const uint32_t ga = (uint32_t)(((2 * s + aKhi) ^ aSwm) << 4);
            LDM_X4(aF[0], sb + aOff0 + ga);
            LDM_X4(aF[1], sb + aOff1 + ga);
            const uint32_t gb = (uint32_t)(((2 * s + bKhi) ^ bSwm) << 4);
            LDM_X4(bF[0], sb + bOff0 + gb);
            LDM_X4(bF[1], sb + bOff1 + gb);
#pragma unroll
            for (int mt = 0; mt < 2; mt++)
#pragma unroll
                for (int q = 0; q < 4; q++) aF[mt][q] = to_tf32_u(aF[mt][q]);
#pragma unroll
            for (int pr = 0; pr < 2; pr++)
#pragma unroll
                for (int q = 0; q < 4; q++) bF[pr][q] = to_tf32_u(bF[pr][q]);
#pragma unroll
            for (int mt = 0; mt < 2; mt++)
#pragma unroll
                for (int nt = 0; nt < 4; nt++) {
                    const int pr = nt >> 1, hf = (nt & 1) * 2;
                    MMA_TF32(acc[mt][nt], aF[mt], bF[pr][hf], bF[pr][hf + 1]);
                }
        }
    }

    // ---- epilogue: write partial sums, layout [j][b] ----
#pragma unroll
    for (int mt = 0; mt < 2; mt++)
#pragma unroll
        for (int nt = 0; nt < 4; nt++) {
            const int j = j0 + wm * 32 + mt * 16 + (lane >> 2);
            const int b = wn * 32 + nt * 8 + (lane & 3) * 2;
            *reinterpret_cast<float2*>(&Cpart[(long)j * B_ + b]) =
                make_float2(acc[mt][nt][0], acc[mt][nt][1]);
            *reinterpret_cast<float2*>(&Cpart[(long)(j + 8) * B_ + b]) =
                make_float2(acc[mt][nt][2], acc[mt][nt][3]);
        }
}

// ---------------------------------------------------------------------------
// out[b][j] = bias[j] + sum_p parts[p][j][b]   (transposing combine)
// ---------------------------------------------------------------------------
__global__ void combine_t_kernel(const float* __restrict__ parts, int nsplit,
                                 const float* __restrict__ bias,
                                 float* __restrict__ out, int N)
{
    int idx = blockIdx.x * 256 + threadIdx.x;
    if (idx >= N * B_) return;
    int j = idx >> 6;
    int b = idx & 63;
    float s = bias[j];
    for (int p = 0; p < nsplit; p++) s += parts[(long)p * N * B_ + idx];
    out[(long)b * N + j] = s;
}

// ---------------------------------------------------------------------------
// GRU gate fusion; gi/gh partials in [p][j(4608)][b] layout.
// ---------------------------------------------------------------------------
__global__ void gru_gate_kernel(const float* __restrict__ giParts,
                                const float* __restrict__ ghParts,
                                const float* __restrict__ b_ih,
                                const float* __restrict__ b_hh,
                                const float* __restrict__ h_prev,   // [b][h]
                                float* __restrict__ h_out)          // [b][h]
{
    int idx = blockIdx.x * 256 + threadIdx.x;
    if (idx >= B_ * H_) return;
    int j = idx >> 6;
    int b = idx & 63;

    float gir = b_ih[j], giz = b_ih[H_ + j], gin = b_ih[2 * H_ + j];
#pragma unroll
    for (int p = 0; p < GI_SPLIT; p++) {
        const float* P = giParts + (long)p * H3_ * B_;
        gir += P[(long)j * B_ + b];
        giz += P[(long)(H_ + j) * B_ + b];
        gin += P[(long)(2 * H_ + j) * B_ + b];
    }
    float ghr = b_hh[j], ghz = b_hh[H_ + j], ghn = b_hh[2 * H_ + j];
#pragma unroll
    for (int p = 0; p < GH_SPLIT; p++) {
        const float* P = ghParts + (long)p * H3_ * B_;
        ghr += P[(long)j * B_ + b];
        ghz += P[(long)(H_ + j) * B_ + b];
        ghn += P[(long)(2 * H_ + j) * B_ + b];
    }

    float r = 1.0f / (1.0f + expf(-(gir + ghr)));
    float z = 1.0f / (1.0f + expf(-(giz + ghz)));
    float n = tanhf(gin + r * ghn);
    float hp = h_prev[(long)b * H_ + j];
    h_out[(long)b * H_ + j] = (1.0f - z) * n + z * hp;
}

// ---------------------------------------------------------------------------
extern "C" void kernel_launch(void* const* d_in, const int* in_sizes, int n_in,
                              void* d_out, int out_size)
{
    const float* x      = (const float*)d_in[0];   // [64,320]
    const float* hidden = (const float*)d_in[1];   // [3,64,1536]
    const float* w_i2h  = (const float*)d_in[2];   // [1536,320]
    const float* b_i2h  = (const float*)d_in[3];   // [1536]
    const float* w_ih   = (const float*)d_in[4];   // [3,4608,1536]
    const float* w_hh   = (const float*)d_in[5];   // [3,4608,1536]
    const float* b_ih   = (const float*)d_in[6];   // [3,4608]
    const float* b_hh   = (const float*)d_in[7];   // [3,4608]
    const float* w_h2o  = (const float*)d_in[8];   // [256,1536]
    const float* b_h2o  = (const float*)d_in[9];   // [256]
    (void)in_sizes; (void)n_in; (void)out_size;

    float* out     = (float*)d_out;                // [64,256]
    float* hid_out = (float*)d_out + B_ * O_;      // [3,64,1536]

    float *gh_ptr, *gi_ptr, *inp_ptr, *outp_ptr;
    cudaGetSymbolAddress((void**)&gh_ptr,   g_gh);
    cudaGetSymbolAddress((void**)&gi_ptr,   g_gi_part);
    cudaGetSymbolAddress((void**)&inp_ptr,  g_inp);
    cudaGetSymbolAddress((void**)&outp_ptr, g_out_part);

    cudaFuncSetAttribute(gemm_tc_kernel, cudaFuncAttributeMaxDynamicSharedMemorySize, SM_TOTAL);

    const long wLayerStride = (long)H3_ * H_;
    const long hLayerStride = (long)B_ * H_;
    const long ghLayerStride = (long)GH_SPLIT * H3_ * B_;

    // 1) gh, all 3 layers, split-K=4: grid (36, 4, 3) = 432 CTAs, 6 chunks each
    gemm_tc_kernel<<<dim3(H3_ / TM, GH_SPLIT, L_), 256, SM_TOTAL>>>(
        hidden, w_hh, gh_ptr, H3_, H_, H_ / GH_SPLIT,
        hLayerStride, wLayerStride, ghLayerStride);

    // 2) i2h: split-K=5: grid (12, 5), 1 chunk each
    gemm_tc_kernel<<<dim3(H_ / TM, I2H_SPLIT, 1), 256, SM_TOTAL>>>(
        x, w_i2h, gi_ptr, H_, I_, I_ / I2H_SPLIT, 0, 0, 0);
    combine_t_kernel<<<(H_ * B_ + 255) / 256, 256>>>(gi_ptr, I2H_SPLIT, b_i2h, inp_ptr, H_);

    // 3) layer chain: gi split-K=4 -> grid (36, 4) = 144 CTAs (one wave), 6 chunks
    const float* inp = inp_ptr;
    for (int l = 0; l < L_; l++) {
        gemm_tc_kernel<<<dim3(H3_ / TM, GI_SPLIT, 1), 256, SM_TOTAL>>>(
            inp, w_ih + (long)l * wLayerStride, gi_ptr,
            H3_, H_, H_ / GI_SPLIT, 0, 0, 0);
        gru_gate_kernel<<<(B_ * H_ + 255) / 256, 256>>>(
            gi_ptr, gh_ptr + (long)l * ghLayerStride,
            b_ih + (long)l * H3_, b_hh + (long)l * H3_,
            hidden + (long)l * hLayerStride,
            hid_out + (long)l * hLayerStride);
        inp = hid_out + (long)l * hLayerStride;
    }

    // 4) h2o: grid (2, 24), 1 chunk each
    gemm_tc_kernel<<<dim3(O_ / TM, H2O_SPLIT, 1), 256, SM_TOTAL>>>(
        inp, w_h2o, outp_ptr, O_, H_, H_ / H2O_SPLIT, 0, 0, 0);
    combine_t_kernel<<<(O_ * B_ + 255) / 256, 256>>>(outp_ptr, H2O_SPLIT, b_h2o, out, O_);
}

// round 12
// speedup vs baseline: 1.8619x; 1.3452x over previous
#include <cuda_runtime.h>
#include <cuda.h>
#include <cuda_bf16.h>
#include <math.h>
#include <stdint.h>

// Problem constants
#define B_  64
#define I_  320
#define H_  1536
#define L_  3
#define O_  256
#define H3_ 4608

#define GH_SPLIT 2
#define GI_SPLIT 8
#define I2H_SPLIT 5
#define H2O_SPLIT 24

#define KC 32            // fp32 k per chunk (128B row; TMA box [32, rows])
#define TM 128           // weight rows per block (MMA M side)
#define STAGE_SZ 24576   // W 128x128B (16KB) + Act 64x128B (8KB)
#define SM_MBAR 98304    // after 4 stages
#define SM_TOTAL (SM_MBAR + 64)

// Device scratch (static, no allocation)
__device__ __align__(16) float g_gh[GH_SPLIT * L_ * H3_ * B_];   // [l][p][j][b]
__device__ __align__(16) float g_gi_part[GI_SPLIT * H3_ * B_];   // [p][j][b]
__device__ __align__(16) float g_inp[B_ * H_];                   // [b][h]
__device__ __align__(16) float g_out_part[H2O_SPLIT * O_ * B_];  // [p][o][b]

__device__ __forceinline__ uint32_t smem_u32(const void* p) {
    uint32_t a;
    asm("{ .reg .u64 t; cvta.to.shared.u64 t, %1; cvt.u32.u64 %0, t; }" : "=r"(a) : "l"(p));
    return a;
}

#define TMA3D(smemaddr, mapptr, x, y, z, mb)                                      \
    asm volatile("cp.async.bulk.tensor.3d.shared::cta.global.tile"                \
                 ".mbarrier::complete_tx::bytes [%0], [%1, {%2, %3, %4}], [%5];"  \
                 :: "r"(smemaddr), "l"(mapptr), "r"(x), "r"(y), "r"(z), "r"(mb)   \
                 : "memory")

#define MBAR_INIT(mb, cnt) \
    asm volatile("mbarrier.init.shared.b64 [%0], %1;" :: "r"(mb), "r"(cnt) : "memory")
#define MBAR_EXPECT(mb, bytes) \
    asm volatile("mbarrier.arrive.expect_tx.shared.b64 _, [%0], %1;" :: "r"(mb), "r"(bytes) : "memory")

__device__ __forceinline__ void mbar_wait(uint32_t mb, uint32_t parity) {
    asm volatile(
        "{\n\t.reg .pred P;\n\t"
        "WL_%=:\n\t"
        "mbarrier.try_wait.parity.acquire.cta.shared::cta.b64 P, [%0], %1, 0x989680;\n\t"
        "@P bra.uni WD_%=;\n\t"
        "bra.uni WL_%=;\n\t"
        "WD_%=:\n\t}"
        :: "r"(mb), "r"(parity) : "memory");
}

#define LDM_X4(r, addr)                                                          \
    asm volatile("ldmatrix.sync.aligned.m8n8.x4.shared.b16 {%0,%1,%2,%3}, [%4];" \
                 : "=r"((r)[0]), "=r"((r)[1]), "=r"((r)[2]), "=r"((r)[3])        \
                 : "r"(addr))

#define MMA_TF32(c, a, b0, b1)                                                   \
    asm volatile("mma.sync.aligned.m16n8k8.row.col.f32.tf32.tf32.f32 "           \
                 "{%0,%1,%2,%3}, {%4,%5,%6,%7}, {%8,%9}, {%0,%1,%2,%3};"         \
                 : "+f"((c)[0]), "+f"((c)[1]), "+f"((c)[2]), "+f"((c)[3])        \
                 : "r"((a)[0]), "r"((a)[1]), "r"((a)[2]), "r"((a)[3]),           \
                   "r"(b0), "r"(b1))

__device__ __forceinline__ uint32_t to_tf32_u(uint32_t x) {
    uint32_t y;
    asm("cvt.rna.tf32.f32 %0, %1;" : "=r"(y) : "f"(__uint_as_float(x)));
    return y;
}

// ---------------------------------------------------------------------------
// TMA-fed tf32 GEMM: Cpart[(z)][y][j][b] = sum_k W[j][k] * Act[b][k]
// W via wmap (K, N, Z), Act via amap (K, 64, Z). 4-stage mbarrier pipeline.
// Block tile 128(j) x 64(b); 8 warps of 32x32.
// ---------------------------------------------------------------------------
__global__ __launch_bounds__(256, 2)
void gemm_tma_kernel(const __grid_constant__ CUtensorMap wmap,
                     const __grid_constant__ CUtensorMap amap,
                     float* __restrict__ Cpart,
                     int N, int kChunk, int zW, int zA, int batched,
                     long cBatchStride)
{
    extern __shared__ __align__(128) unsigned char smem[];
    const uint32_t smemB = smem_u32(smem);

    const int tid  = threadIdx.x;
    const int wid  = tid >> 5;
    const int lane = tid & 31;
    const int j0    = blockIdx.x * TM;
    const int kBase = blockIdx.y * kChunk;
    const int nChunks = kChunk >> 5;

    const int zw = batched ? blockIdx.z : zW;
    const int za = batched ? blockIdx.z : zA;
    if (batched) Cpart += (long)blockIdx.z * cBatchStride;
    Cpart += (long)blockIdx.y * (long)N * B_;

    if (tid == 0) {
#pragma unroll
        for (int i = 0; i < 4; i++) MBAR_INIT(smemB + SM_MBAR + i * 8, 1);
    }
    __syncthreads();

    // ---- producer: one thread, one 16KB W box + one 8KB Act box per stage ----
    auto issue = [&](int c) {
        const int st = c & 3;
        const uint32_t mb = smemB + SM_MBAR + st * 8;
        MBAR_EXPECT(mb, 24576u);
        const uint32_t sb = smemB + (uint32_t)st * STAGE_SZ;
        TMA3D(sb,         &wmap, kBase + c * KC, j0, zw, mb);
        TMA3D(sb + 16384, &amap, kBase + c * KC, 0,  za, mb);
    };

    if (tid == 0) {
        for (int p = 0; p < 3 && p < nChunks; p++) issue(p);
    }

    // ---- mma mapping: 8 warps = 4(M) x 2(N); warp tile 32x32 ----
    const int wm = wid & 3, wn = wid >> 2;
    const int r7 = lane & 7;
    const int aKhi = lane >> 4;
    const int bKhi = (lane >> 3) & 1;
    const int bNoff = (lane & 7) + ((lane >> 4) << 3);
    const uint32_t aOff0 = (uint32_t)(wm * 32 + (lane & 15)) * 128;
    const uint32_t aOff1 = aOff0 + 2048;
    const uint32_t bOff0 = 16384 + (uint32_t)(wn * 32 + bNoff) * 128;
    const uint32_t bOff1 = bOff0 + 2048;

    float acc[2][4][4];
#pragma unroll
    for (int mt = 0; mt < 2; mt++)
#pragma unroll
        for (int nt = 0; nt < 4; nt++)
#pragma unroll
            for (int q = 0; q < 4; q++) acc[mt][nt][q] = 0.0f;

    for (int c = 0; c < nChunks; ++c) {
        if (c) __syncthreads();            // all warps done with MMA(c-1)
        if (c + 3 < nChunks && tid == 0) issue(c + 3);   // overwrites stage (c-1)&3

        mbar_wait(smemB + SM_MBAR + (c & 3) * 8, (uint32_t)(c >> 2) & 1);

        // ---- MMA on stage c&3: 4 k8 steps ----
        const uint32_t sb = smemB + (uint32_t)(c & 3) * STAGE_SZ;
#pragma unroll
        for (int s = 0; s < 4; s++) {
            uint32_t aF[2][4], bF[2][4];
            const uint32_t ga = (uint32_t)(((2 * s + aKhi) ^ r7) << 4);
            LDM_X4(aF[0], sb + aOff0 + ga);
            LDM_X4(aF[1], sb + aOff1 + ga);
            const uint32_t gb = (uint32_t)(((2 * s + bKhi) ^ r7) << 4);
            LDM_X4(bF[0], sb + bOff0 + gb);
            LDM_X4(bF[1], sb + bOff1 + gb);
#pragma unroll
            for (int mt = 0; mt < 2; mt++)
#pragma unroll
                for (int q = 0; q < 4; q++) aF[mt][q] = to_tf32_u(aF[mt][q]);
#pragma unroll
            for (int pr = 0; pr < 2; pr++)
#pragma unroll
                for (int q = 0; q < 4; q++) bF[pr][q] = to_tf32_u(bF[pr][q]);
#pragma unroll
            for (int mt = 0; mt < 2; mt++)
#pragma unroll
                for (int nt = 0; nt < 4; nt++) {
                    const int pr = nt >> 1, hf = (nt & 1) * 2;
                    MMA_TF32(acc[mt][nt], aF[mt], bF[pr][hf], bF[pr][hf + 1]);
                }
        }
    }

    // ---- epilogue: write partial sums, layout [j][b] ----
#pragma unroll
    for (int mt = 0; mt < 2; mt++)
#pragma unroll
        for (int nt = 0; nt < 4; nt++) {
            const int j = j0 + wm * 32 + mt * 16 + (lane >> 2);
            const int b = wn * 32 + nt * 8 + (lane & 3) * 2;
            *reinterpret_cast<float2*>(&Cpart[(long)j * B_ + b]) =
                make_float2(acc[mt][nt][0], acc[mt][nt][1]);
            *reinterpret_cast<float2*>(&Cpart[(long)(j + 8) * B_ + b]) =
                make_float2(acc[mt][nt][2], acc[mt][nt][3]);
        }
}

// ---------------------------------------------------------------------------
// out[b][j] = bias[j] + sum_p parts[p][j][b]   (transposing combine)
// ---------------------------------------------------------------------------
__global__ void combine_t_kernel(const float* __restrict__ parts, int nsplit,
                                 const float* __restrict__ bias,
                                 float* __restrict__ out, int N)
{
    int idx = blockIdx.x * 256 + threadIdx.x;
    if (idx >= N * B_) return;
    int j = idx >> 6;
    int b = idx & 63;
    float s = bias[j];
    for (int p = 0; p < nsplit; p++) s += parts[(long)p * N * B_ + idx];
    out[(long)b * N + j] = s;
}

// ---------------------------------------------------------------------------
// GRU gate fusion; gi/gh partials in [p][j(4608)][b] layout.
// ---------------------------------------------------------------------------
__global__ void gru_gate_kernel(const float* __restrict__ giParts,
                                const float* __restrict__ ghParts,
                                const float* __restrict__ b_ih,
                                const float* __restrict__ b_hh,
                                const float* __restrict__ h_prev,   // [b][h]
                                float* __restrict__ h_out)          // [b][h]
{
    int idx = blockIdx.x * 256 + threadIdx.x;
    if (idx >= B_ * H_) return;
    int j = idx >> 6;
    int b = idx & 63;

    float gir = b_ih[j], giz = b_ih[H_ + j], gin = b_ih[2 * H_ + j];
#pragma unroll
    for (int p = 0; p < GI_SPLIT; p++) {
        const float* P = giParts + (long)p * H3_ * B_;
        gir += P[(long)j * B_ + b];
        giz += P[(long)(H_ + j) * B_ + b];
        gin += P[(long)(2 * H_ + j) * B_ + b];
    }
    float ghr = b_hh[j], ghz = b_hh[H_ + j], ghn = b_hh[2 * H_ + j];
#pragma unroll
    for (int p = 0; p < GH_SPLIT; p++) {
        const float* P = ghParts + (long)p * H3_ * B_;
        ghr += P[(long)j * B_ + b];
        ghz += P[(long)(H_ + j) * B_ + b];
        ghn += P[(long)(2 * H_ + j) * B_ + b];
    }

    float r = 1.0f / (1.0f + expf(-(gir + ghr)));
    float z = 1.0f / (1.0f + expf(-(giz + ghz)));
    float n = tanhf(gin + r * ghn);
    float hp = h_prev[(long)b * H_ + j];
    h_out[(long)b * H_ + j] = (1.0f - z) * n + z * hp;
}

// ---------------------------------------------------------------------------
// Host-side tensormap encoding via runtime driver-entry-point (no -lcuda).
// ---------------------------------------------------------------------------
typedef CUresult (*PFN_encodeTiled)(
    CUtensorMap*, CUtensorMapDataType, unsigned int, void*,
    const unsigned long long*, const unsigned long long*,
    const unsigned int*, const unsigned int*,
    CUtensorMapInterleave, CUtensorMapSwizzle,
    CUtensorMapL2promotion, CUtensorMapFloatOOBfill);

static PFN_encodeTiled get_encoder() {
    void* fp = nullptr;
    cudaDriverEntryPointQueryResult st;
    cudaGetDriverEntryPointByVersion("cuTensorMapEncodeTiled", &fp, 12000,
                                     cudaEnableDefault, &st);
    return (PFN_encodeTiled)fp;
}

static void enc3d(PFN_encodeTiled f, CUtensorMap* m, const void* base,
                  unsigned long long d0, unsigned long long d1,
                  unsigned long long d2, unsigned int boxN)
{
    unsigned long long dims[3]    = {d0, d1, d2};
    unsigned long long strides[2] = {d0 * 4ull, d0 * 4ull * d1};
    unsigned int box[3] = {32u, boxN, 1u};
    unsigned int es[3]  = {1u, 1u, 1u};
    f(m, CU_TENSOR_MAP_DATA_TYPE_FLOAT32, 3, const_cast<void*>(base),
      dims, strides, box, es,
      CU_TENSOR_MAP_INTERLEAVE_NONE, CU_TENSOR_MAP_SWIZZLE_128B,
      CU_TENSOR_MAP_L2_PROMOTION_L2_128B, CU_TENSOR_MAP_FLOAT_OOB_FILL_NONE);
}

// ---------------------------------------------------------------------------
extern "C" void kernel_launch(void* const* d_in, const int* in_sizes, int n_in,
                              void* d_out, int out_size)
{
    const float* x      = (const float*)d_in[0];   // [64,320]
    const float* hidden = (const float*)d_in[1];   // [3,64,1536]
    const float* w_i2h  = (const float*)d_in[2];   // [1536,320]
    const float* b_i2h  = (const float*)d_in[3];   // [1536]
    const float* w_ih   = (const float*)d_in[4];   // [3,4608,1536]
    const float* w_hh   = (const float*)d_in[5];   // [3,4608,1536]
    const float* b_ih   = (const float*)d_in[6];   // [3,4608]
    const float* b_hh   = (const float*)d_in[7];   // [3,4608]
    const float* w_h2o  = (const float*)d_in[8];   // [256,1536]
    const float* b_h2o  = (const float*)d_in[9];   // [256]
    (void)in_sizes; (void)n_in; (void)out_size;

    float* out     = (float*)d_out;                // [64,256]
    float* hid_out = (float*)d_out + B_ * O_;      // [3,64,1536]

    float *gh_ptr, *gi_ptr, *inp_ptr, *outp_ptr;
    cudaGetSymbolAddress((void**)&gh_ptr,   g_gh);
    cudaGetSymbolAddress((void**)&gi_ptr,   g_gi_part);
    cudaGetSymbolAddress((void**)&inp_ptr,  g_inp);
    cudaGetSymbolAddress((void**)&outp_ptr, g_out_part);

    cudaFuncSetAttribute(gemm_tma_kernel, cudaFuncAttributeMaxDynamicSharedMemorySize, SM_TOTAL);

    PFN_encodeTiled f = get_encoder();
    static CUtensorMap mWhh, mHid, mWih, mWi2h, mX, mWh2o, mInp, mHidO;
    enc3d(f, &mWhh,  w_hh,    H_, H3_, L_, 128);   // (k, j, layer)
    enc3d(f, &mHid,  hidden,  H_, B_,  L_, 64);
    enc3d(f, &mWih,  w_ih,    H_, H3_, L_, 128);
    enc3d(f, &mWi2h, w_i2h,   I_, H_,  1,  128);
    enc3d(f, &mX,    x,       I_, B_,  1,  64);
    enc3d(f, &mWh2o, w_h2o,   H_, O_,  1,  128);
    enc3d(f, &mInp,  inp_ptr, H_, B_,  1,  64);
    enc3d(f, &mHidO, hid_out, H_, B_,  L_, 64);

    const long hLayerStride = (long)B_ * H_;
    const long ghLayerStride = (long)GH_SPLIT * H3_ * B_;

    // 1) gh, all 3 layers, split-K=2: grid (36, 2, 3)
    gemm_tma_kernel<<<dim3(H3_ / TM, GH_SPLIT, L_), 256, SM_TOTAL>>>(
        mWhh, mHid, gh_ptr, H3_, H_ / GH_SPLIT, 0, 0, 1, ghLayerStride);

    // 2) i2h: split-K=5: grid (12, 5)
    gemm_tma_kernel<<<dim3(H_ / TM, I2H_SPLIT, 1), 256, SM_TOTAL>>>(
        mWi2h, mX, gi_ptr, H_, I_ / I2H_SPLIT, 0, 0, 0, 0);
    combine_t_kernel<<<(H_ * B_ + 255) / 256, 256>>>(gi_ptr, I2H_SPLIT, b_i2h, inp_ptr, H_);

    // 3) layer chain: gi split-K=8 -> grid (36, 8) = 288 CTAs
    for (int l = 0; l < L_; l++) {
        const int zA = (l == 0) ? 0 : (l - 1);   // FIX: mInp has z-dim 1 -> z must be 0
        gemm_tma_kernel<<<dim3(H3_ / TM, GI_SPLIT, 1), 256, SM_TOTAL>>>(
            mWih, (l == 0) ? mInp : mHidO, gi_ptr,
            H3_, H_ / GI_SPLIT, l, zA, 0, 0);
        gru_gate_kernel<<<(B_ * H_ + 255) / 256, 256>>>(
            gi_ptr, gh_ptr + (long)l * ghLayerStride,
            b_ih + (long)l * H3_, b_hh + (long)l * H3_,
            hidden + (long)l * hLayerStride,
            hid_out + (long)l * hLayerStride);
    }

    // 4) h2o: grid (2, 24); Act = hid_out layer 2
    gemm_tma_kernel<<<dim3(O_ / TM, H2O_SPLIT, 1), 256, SM_TOTAL>>>(
        mWh2o, mHidO, outp_ptr, O_, H_ / H2O_SPLIT, 0, 2, 0, 0);
    combine_t_kernel<<<(O_ * B_ + 255) / 256, 256>>>(outp_ptr, H2O_SPLIT, b_h2o, out, O_);
}

// round 13
// speedup vs baseline: 1.9837x; 1.0654x over previous
#include <cuda_runtime.h>
#include <cuda.h>
#include <cuda_bf16.h>
#include <math.h>
#include <stdint.h>

// Problem constants
#define B_  64
#define I_  320
#define H_  1536
#define L_  3
#define O_  256
#define H3_ 4608

#define GH_SPLIT 4
#define GI_SPLIT 8
#define I2H_SPLIT 5
#define H2O_SPLIT 24

#define KC 32            // fp32 k per chunk (128B row; TMA box [32, rows])
#define TM 128           // weight rows per block (MMA M side)
#define STAGE_SZ 24576   // W 128x128B (16KB) + Act 64x128B (8KB)
#define SM_MBAR  98304   // 4 full barriers (8B each)
#define SM_MBARE 98336   // 4 empty barriers
#define SM_TOTAL 98432

// Device scratch (static, no allocation)
__device__ __align__(16) float g_gh[GH_SPLIT * L_ * H3_ * B_];   // [l][p][j][b]
__device__ __align__(16) float g_gi_part[GI_SPLIT * H3_ * B_];   // [p][j][b]
__device__ __align__(16) float g_inp[B_ * H_];                   // [b][h]
__device__ __align__(16) float g_out_part[H2O_SPLIT * O_ * B_];  // [p][o][b]

__device__ __forceinline__ uint32_t smem_u32(const void* p) {
    uint32_t a;
    asm("{ .reg .u64 t; cvta.to.shared.u64 t, %1; cvt.u32.u64 %0, t; }" : "=r"(a) : "l"(p));
    return a;
}

#define TMA3D(smemaddr, mapptr, x, y, z, mb)                                      \
    asm volatile("cp.async.bulk.tensor.3d.shared::cta.global.tile"                \
                 ".mbarrier::complete_tx::bytes [%0], [%1, {%2, %3, %4}], [%5];"  \
                 :: "r"(smemaddr), "l"(mapptr), "r"(x), "r"(y), "r"(z), "r"(mb)   \
                 : "memory")

#define MBAR_INIT(mb, cnt) \
    asm volatile("mbarrier.init.shared.b64 [%0], %1;" :: "r"(mb), "r"(cnt) : "memory")
#define MBAR_EXPECT(mb, bytes) \
    asm volatile("mbarrier.arrive.expect_tx.shared.b64 _, [%0], %1;" :: "r"(mb), "r"(bytes) : "memory")
#define MBAR_ARRIVE(mb) \
    asm volatile("mbarrier.arrive.release.cta.shared::cta.b64 _, [%0];" :: "r"(mb) : "memory")

__device__ __forceinline__ void mbar_wait(uint32_t mb, uint32_t parity) {
    asm volatile(
        "{\n\t.reg .pred P;\n\t"
        "WL_%=:\n\t"
        "mbarrier.try_wait.parity.acquire.cta.shared::cta.b64 P, [%0], %1, 0x989680;\n\t"
        "@P bra.uni WD_%=;\n\t"
        "bra.uni WL_%=;\n\t"
        "WD_%=:\n\t}"
        :: "r"(mb), "r"(parity) : "memory");
}

#define LDM_X4(r, addr)                                                          \
    asm volatile("ldmatrix.sync.aligned.m8n8.x4.shared.b16 {%0,%1,%2,%3}, [%4];" \
                 : "=r"((r)[0]), "=r"((r)[1]), "=r"((r)[2]), "=r"((r)[3])        \
                 : "r"(addr))

#define MMA_TF32(c, a, b0, b1)                                                   \
    asm volatile("mma.sync.aligned.m16n8k8.row.col.f32.tf32.tf32.f32 "           \
                 "{%0,%1,%2,%3}, {%4,%5,%6,%7}, {%8,%9}, {%0,%1,%2,%3};"         \
                 : "+f"((c)[0]), "+f"((c)[1]), "+f"((c)[2]), "+f"((c)[3])        \
                 : "r"((a)[0]), "r"((a)[1]), "r"((a)[2]), "r"((a)[3]),           \
                   "r"(b0), "r"(b1))

__device__ __forceinline__ uint32_t to_tf32_u(uint32_t x) {
    uint32_t y;
    asm("cvt.rna.tf32.f32 %0, %1;" : "=r"(y) : "f"(__uint_as_float(x)));
    return y;
}

// ---------------------------------------------------------------------------
// TMA-fed tf32 GEMM: Cpart[(z)][y][j][b] = sum_k W[j][k] * Act[b][k]
// 4-stage full/empty mbarrier pipeline (no per-chunk __syncthreads:
// warps de-skew up to pipeline depth). Block tile 128(j) x 64(b).
// ---------------------------------------------------------------------------
__global__ __launch_bounds__(256, 2)
void gemm_tma_kernel(const __grid_constant__ CUtensorMap wmap,
                     const __grid_constant__ CUtensorMap amap,
                     float* __restrict__ Cpart,
                     int N, int kChunk, int zW, int zA, int batched,
                     long cBatchStride)
{
    extern __shared__ __align__(128) unsigned char smem[];
    const uint32_t smemB = smem_u32(smem);

    const int tid  = threadIdx.x;
    const int wid  = tid >> 5;
    const int lane = tid & 31;
    const int j0    = blockIdx.x * TM;
    const int kBase = blockIdx.y * kChunk;
    const int nChunks = kChunk >> 5;

    const int zw = batched ? blockIdx.z : zW;
    const int za = batched ? blockIdx.z : zA;
    if (batched) Cpart += (long)blockIdx.z * cBatchStride;
    Cpart += (long)blockIdx.y * (long)N * B_;

    if (tid == 0) {
#pragma unroll
        for (int i = 0; i < 4; i++) {
            MBAR_INIT(smemB + SM_MBAR  + i * 8, 1);   // full: producer arrive+tx
            MBAR_INIT(smemB + SM_MBARE + i * 8, 8);   // empty: one arrive per warp
        }
    }
    __syncthreads();

    // ---- producer: one 16KB W box + one 8KB Act box per stage ----
    auto issue = [&](int c) {
        const int st = c & 3;
        const uint32_t mb = smemB + SM_MBAR + st * 8;
        MBAR_EXPECT(mb, 24576u);
        const uint32_t sb = smemB + (uint32_t)st * STAGE_SZ;
        TMA3D(sb,         &wmap, kBase + c * KC, j0, zw, mb);
        TMA3D(sb + 16384, &amap, kBase + c * KC, 0,  za, mb);
    };

    if (tid == 0) {
        for (int p = 0; p < 3 && p < nChunks; p++) issue(p);
    }

    // ---- mma mapping: 8 warps = 4(M) x 2(N); warp tile 32x32 ----
    const int wm = wid & 3, wn = wid >> 2;
    const int r7 = lane & 7;
    const int aKhi = lane >> 4;
    const int bKhi = (lane >> 3) & 1;
    const int bNoff = (lane & 7) + ((lane >> 4) << 3);
    const uint32_t aOff0 = (uint32_t)(wm * 32 + (lane & 15)) * 128;
    const uint32_t aOff1 = aOff0 + 2048;
    const uint32_t bOff0 = 16384 + (uint32_t)(wn * 32 + bNoff) * 128;
    const uint32_t bOff1 = bOff0 + 2048;

    float acc[2][4][4];
#pragma unroll
    for (int mt = 0; mt < 2; mt++)
#pragma unroll
        for (int nt = 0; nt < 4; nt++)
#pragma unroll
            for (int q = 0; q < 4; q++) acc[mt][nt][q] = 0.0f;

    for (int c = 0; c < nChunks; ++c) {
        // producer refill: wait until all warps released stage, then issue
        if (tid == 0 && c + 3 < nChunks) {
            const int X = c + 3;
            mbar_wait(smemB + SM_MBARE + (X & 3) * 8, (uint32_t)((X >> 2) + 1) & 1);
            issue(X);
        }

        mbar_wait(smemB + SM_MBAR + (c & 3) * 8, (uint32_t)(c >> 2) & 1);

        // ---- MMA on stage c&3: 4 k8 steps ----
        const uint32_t sb = smemB + (uint32_t)(c & 3) * STAGE_SZ;
#pragma unroll
        for (int s = 0; s < 4; s++) {
            uint32_t aF[2][4], bF[2][4];
            const uint32_t ga = (uint32_t)(((2 * s + aKhi) ^ r7) << 4);
            LDM_X4(aF[0], sb + aOff0 + ga);
            LDM_X4(aF[1], sb + aOff1 + ga);
            const uint32_t gb = (uint32_t)(((2 * s + bKhi) ^ r7) << 4);
            LDM_X4(bF[0], sb + bOff0 + gb);
            LDM_X4(bF[1], sb + bOff1 + gb);
#pragma unroll
            for (int mt = 0; mt < 2; mt++)
#pragma unroll
                for (int q = 0; q < 4; q++) aF[mt][q] = to_tf32_u(aF[mt][q]);
#pragma unroll
            for (int pr = 0; pr < 2; pr++)
#pragma unroll
                for (int q = 0; q < 4; q++) bF[pr][q] = to_tf32_u(bF[pr][q]);
#pragma unroll
            for (int mt = 0; mt < 2; mt++)
#pragma unroll
                for (int nt = 0; nt < 4; nt++) {
                    const int pr = nt >> 1, hf = (nt & 1) * 2;
                    MMA_TF32(acc[mt][nt], aF[mt], bF[pr][hf], bF[pr][hf + 1]);
                }
        }

        // release stage: one arrive per warp (reads done — LDSM results in regs)
        __syncwarp();
        if (lane == 0) MBAR_ARRIVE(smemB + SM_MBARE + (c & 3) * 8);
    }

    // ---- epilogue: write partial sums, layout [j][b] ----
#pragma unroll
    for (int mt = 0; mt < 2; mt++)
#pragma unroll
        for (int nt = 0; nt < 4; nt++) {
            const int j = j0 + wm * 32 + mt * 16 + (lane >> 2);
            const int b = wn * 32 + nt * 8 + (lane & 3) * 2;
            *reinterpret_cast<float2*>(&Cpart[(long)j * B_ + b]) =
                make_float2(acc[mt][nt][0], acc[mt][nt][1]);
            *reinterpret_cast<float2*>(&Cpart[(long)(j + 8) * B_ + b]) =
                make_float2(acc[mt][nt][2], acc[mt][nt][3]);
        }
}

// ---------------------------------------------------------------------------
// out[b][j] = bias[j] + sum_p parts[p][j][b]   (transposing combine)
// ---------------------------------------------------------------------------
__global__ void combine_t_kernel(const float* __restrict__ parts, int nsplit,
                                 const float* __restrict__ bias,
                                 float* __restrict__ out, int N)
{
    int idx = blockIdx.x * 256 + threadIdx.x;
    if (idx >= N * B_) return;
    int j = idx >> 6;
    int b = idx & 63;
    float s = bias[j];
    for (int p = 0; p < nsplit; p++) s += parts[(long)p * N * B_ + idx];
    out[(long)b * N + j] = s;
}

// ---------------------------------------------------------------------------
// GRU gate fusion; gi/gh partials in [p][j(4608)][b] layout.
// ---------------------------------------------------------------------------
__global__ void gru_gate_kernel(const float* __restrict__ giParts,
                                const float* __restrict__ ghParts,
                                const float* __restrict__ b_ih,
                                const float* __restrict__ b_hh,
                                const float* __restrict__ h_prev,   // [b][h]
                                float* __restrict__ h_out)          // [b][h]
{
    int idx = blockIdx.x * 256 + threadIdx.x;
    if (idx >= B_ * H_) return;
    int j = idx >> 6;
    int b = idx & 63;

    float gir = b_ih[j], giz = b_ih[H_ + j], gin = b_ih[2 * H_ + j];
#pragma unroll
    for (int p = 0; p < GI_SPLIT; p++) {
        const float* P = giParts + (long)p * H3_ * B_;
        gir += P[(long)j * B_ + b];
        giz += P[(long)(H_ + j) * B_ + b];
        gin += P[(long)(2 * H_ + j) * B_ + b];
    }
    float ghr = b_hh[j], ghz = b_hh[H_ + j], ghn = b_hh[2 * H_ + j];
#pragma unroll
    for (int p = 0; p < GH_SPLIT; p++) {
        const float* P = ghParts + (long)p * H3_ * B_;
        ghr += P[(long)j * B_ + b];
        ghz += P[(long)(H_ + j) * B_ + b];
        ghn += P[(long)(2 * H_ + j) * B_ + b];
    }

    float r = 1.0f / (1.0f + expf(-(gir + ghr)));
    float z = 1.0f / (1.0f + expf(-(giz + ghz)));
    float n = tanhf(gin + r * ghn);
    float hp = h_prev[(long)b * H_ + j];
    h_out[(long)b * H_ + j] = (1.0f - z) * n + z * hp;
}

// ---------------------------------------------------------------------------
// Host-side tensormap encoding via runtime driver-entry-point (no -lcuda).
// ---------------------------------------------------------------------------
typedef CUresult (*PFN_encodeTiled)(
    CUtensorMap*, CUtensorMapDataType, unsigned int, void*,
    const unsigned long long*, const unsigned long long*,
    const unsigned int*, const unsigned int*,
    CUtensorMapInterleave, CUtensorMapSwizzle,
    CUtensorMapL2promotion, CUtensorMapFloatOOBfill);

static PFN_encodeTiled get_encoder() {
    void* fp = nullptr;
    cudaDriverEntryPointQueryResult st;
    cudaGetDriverEntryPointByVersion("cuTensorMapEncodeTiled", &fp, 12000,
                                     cudaEnableDefault, &st);
    return (PFN_encodeTiled)fp;
}

static void enc3d(PFN_encodeTiled f, CUtensorMap* m, const void* base,
                  unsigned long long d0, unsigned long long d1,
                  unsigned long long d2, unsigned int boxN)
{
    unsigned long long dims[3]    = {d0, d1, d2};
    unsigned long long strides[2] = {d0 * 4ull, d0 * 4ull * d1};
    unsigned int box[3] = {32u, boxN, 1u};
    unsigned int es[3]  = {1u, 1u, 1u};
    f(m, CU_TENSOR_MAP_DATA_TYPE_FLOAT32, 3, const_cast<void*>(base),
      dims, strides, box, es,
      CU_TENSOR_MAP_INTERLEAVE_NONE, CU_TENSOR_MAP_SWIZZLE_128B,
      CU_TENSOR_MAP_L2_PROMOTION_L2_128B, CU_TENSOR_MAP_FLOAT_OOB_FILL_NONE);
}

// ---------------------------------------------------------------------------
extern "C" void kernel_launch(void* const* d_in, const int* in_sizes, int n_in,
                              void* d_out, int out_size)
{
    const float* x      = (const float*)d_in[0];   // [64,320]
    const float* hidden = (const float*)d_in[1];   // [3,64,1536]
    const float* w_i2h  = (const float*)d_in[2];   // [1536,320]
    const float* b_i2h  = (const float*)d_in[3];   // [1536]
    const float* w_ih   = (const float*)d_in[4];   // [3,4608,1536]
    const float* w_hh   = (const float*)d_in[5];   // [3,4608,1536]
    const float* b_ih   = (const float*)d_in[6];   // [3,4608]
    const float* b_hh   = (const float*)d_in[7];   // [3,4608]
    const float* w_h2o  = (const float*)d_in[8];   // [256,1536]
    const float* b_h2o  = (const float*)d_in[9];   // [256]
    (void)in_sizes; (void)n_in; (void)out_size;

    float* out     = (float*)d_out;                // [64,256]
    float* hid_out = (float*)d_out + B_ * O_;      // [3,64,1536]

    float *gh_ptr, *gi_ptr, *inp_ptr, *outp_ptr;
    cudaGetSymbolAddress((void**)&gh_ptr,   g_gh);
    cudaGetSymbolAddress((void**)&gi_ptr,   g_gi_part);
    cudaGetSymbolAddress((void**)&inp_ptr,  g_inp);
    cudaGetSymbolAddress((void**)&outp_ptr, g_out_part);

    cudaFuncSetAttribute(gemm_tma_kernel, cudaFuncAttributeMaxDynamicSharedMemorySize, SM_TOTAL);

    PFN_encodeTiled f = get_encoder();
    static CUtensorMap mWhh, mHid, mWih, mWi2h, mX, mWh2o, mInp, mHidO;
    enc3d(f, &mWhh,  w_hh,    H_, H3_, L_, 128);   // (k, j, layer)
    enc3d(f, &mHid,  hidden,  H_, B_,  L_, 64);
    enc3d(f, &mWih,  w_ih,    H_, H3_, L_, 128);
    enc3d(f, &mWi2h, w_i2h,   I_, H_,  1,  128);
    enc3d(f, &mX,    x,       I_, B_,  1,  64);
    enc3d(f, &mWh2o, w_h2o,   H_, O_,  1,  128);
    enc3d(f, &mInp,  inp_ptr, H_, B_,  1,  64);
    enc3d(f, &mHidO, hid_out, H_, B_,  L_, 64);

    const long hLayerStride = (long)B_ * H_;
    const long ghLayerStride = (long)GH_SPLIT * H3_ * B_;

    // 1) gh, all 3 layers, split-K=4: grid (36, 4, 3) = 432 CTAs, 12 chunks
    gemm_tma_kernel<<<dim3(H3_ / TM, GH_SPLIT, L_), 256, SM_TOTAL>>>(
        mWhh, mHid, gh_ptr, H3_, H_ / GH_SPLIT, 0, 0, 1, ghLayerStride);

    // 2) i2h: split-K=5: grid (12, 5)
    gemm_tma_kernel<<<dim3(H_ / TM, I2H_SPLIT, 1), 256, SM_TOTAL>>>(
        mWi2h, mX, gi_ptr, H_, I_ / I2H_SPLIT, 0, 0, 0, 0);
    combine_t_kernel<<<(H_ * B_ + 255) / 256, 256>>>(gi_ptr, I2H_SPLIT, b_i2h, inp_ptr, H_);

    // 3) layer chain: gi split-K=8 -> grid (36, 8) = 288 CTAs, 6 chunks
    for (int l = 0; l < L_; l++) {
        const int zA = (l == 0) ? 0 : (l - 1);
        gemm_tma_kernel<<<dim3(H3_ / TM, GI_SPLIT, 1), 256, SM_TOTAL>>>(
            mWih, (l == 0) ? mInp : mHidO, gi_ptr,
            H3_, H_ / GI_SPLIT, l, zA, 0, 0);
        gru_gate_kernel<<<(B_ * H_ + 255) / 256, 256>>>(
            gi_ptr, gh_ptr + (long)l * ghLayerStride,
            b_ih + (long)l * H3_, b_hh + (long)l * H3_,
            hidden + (long)l * hLayerStride,
            hid_out + (long)l * hLayerStride);
    }

    // 4) h2o: grid (2, 24); Act = hid_out layer 2
    gemm_tma_kernel<<<dim3(O_ / TM, H2O_SPLIT, 1), 256, SM_TOTAL>>>(
        mWh2o, mHidO, outp_ptr, O_, H_ / H2O_SPLIT, 0, 2, 0, 0);
    combine_t_kernel<<<(O_ * B_ + 255) / 256, 256>>>(outp_ptr, H2O_SPLIT, b_h2o, out, O_);
}

// round 14
// speedup vs baseline: 2.0636x; 1.0403x over previous
#include <cuda_runtime.h>
#include <cuda.h>
#include <cuda_bf16.h>
#include <math.h>
#include <stdint.h>

// Problem constants
#define B_  64
#define I_  320
#define H_  1536
#define L_  3
#define O_  256
#define H3_ 4608

#define GH_SPLIT 4
#define GI_SPLIT 8
#define I2H_SPLIT 5
#define H2O_SPLIT 24

#define KC 32            // fp32 k per chunk (128B row; TMA box [32, rows])
#define TM 128           // weight rows per block (MMA M side)
#define STAGE_SZ 24576   // W 128x128B (16KB) + Act 64x128B (8KB)
#define SM_MBAR  98304   // 4 full barriers (8B each)
#define SM_MBARE 98336   // 4 empty barriers
#define SM_TOTAL 98432

// Device scratch (static, no allocation)
__device__ __align__(16) float g_gh[GH_SPLIT * L_ * H3_ * B_];   // [l][p][j][b]
__device__ __align__(16) float g_gi_part[GI_SPLIT * H3_ * B_];   // [p][j][b]
__device__ __align__(16) float g_inp[B_ * H_];                   // [b][h]
__device__ __align__(16) float g_out_part[H2O_SPLIT * O_ * B_];  // [p][o][b]

__device__ __forceinline__ uint32_t smem_u32(const void* p) {
    uint32_t a;
    asm("{ .reg .u64 t; cvta.to.shared.u64 t, %1; cvt.u32.u64 %0, t; }" : "=r"(a) : "l"(p));
    return a;
}

#define TMA3D(smemaddr, mapptr, x, y, z, mb)                                      \
    asm volatile("cp.async.bulk.tensor.3d.shared::cta.global.tile"                \
                 ".mbarrier::complete_tx::bytes [%0], [%1, {%2, %3, %4}], [%5];"  \
                 :: "r"(smemaddr), "l"(mapptr), "r"(x), "r"(y), "r"(z), "r"(mb)   \
                 : "memory")

#define MBAR_INIT(mb, cnt) \
    asm volatile("mbarrier.init.shared.b64 [%0], %1;" :: "r"(mb), "r"(cnt) : "memory")
#define MBAR_EXPECT(mb, bytes) \
    asm volatile("mbarrier.arrive.expect_tx.shared.b64 _, [%0], %1;" :: "r"(mb), "r"(bytes) : "memory")
#define MBAR_ARRIVE(mb) \
    asm volatile("mbarrier.arrive.release.cta.shared::cta.b64 _, [%0];" :: "r"(mb) : "memory")

__device__ __forceinline__ void mbar_wait(uint32_t mb, uint32_t parity) {
    asm volatile(
        "{\n\t.reg .pred P;\n\t"
        "WL_%=:\n\t"
        "mbarrier.try_wait.parity.acquire.cta.shared::cta.b64 P, [%0], %1, 0x989680;\n\t"
        "@P bra.uni WD_%=;\n\t"
        "bra.uni WL_%=;\n\t"
        "WD_%=:\n\t}"
        :: "r"(mb), "r"(parity) : "memory");
}

#define LDM_X4(r, addr)                                                          \
    asm volatile("ldmatrix.sync.aligned.m8n8.x4.shared.b16 {%0,%1,%2,%3}, [%4];" \
                 : "=r"((r)[0]), "=r"((r)[1]), "=r"((r)[2]), "=r"((r)[3])        \
                 : "r"(addr))

#define MMA_TF32(c, a, b0, b1)                                                   \
    asm volatile("mma.sync.aligned.m16n8k8.row.col.f32.tf32.tf32.f32 "           \
                 "{%0,%1,%2,%3}, {%4,%5,%6,%7}, {%8,%9}, {%0,%1,%2,%3};"         \
                 : "+f"((c)[0]), "+f"((c)[1]), "+f"((c)[2]), "+f"((c)[3])        \
                 : "r"((a)[0]), "r"((a)[1]), "r"((a)[2]), "r"((a)[3]),           \
                   "r"(b0), "r"(b1))

__device__ __forceinline__ uint32_t to_tf32_u(uint32_t x) {
    uint32_t y;
    asm("cvt.rna.tf32.f32 %0, %1;" : "=r"(y) : "f"(__uint_as_float(x)));
    return y;
}

// ---------------------------------------------------------------------------
// TMA-fed tf32 GEMM: Cpart[(z)][y][j][b] = sum_k W[j][k] * Act[b][k]
// 4-stage full/empty mbarrier pipeline (no per-chunk __syncthreads:
// warps de-skew up to pipeline depth). Block tile 128(j) x 64(b).
// ---------------------------------------------------------------------------
__global__ __launch_bounds__(256, 2)
void gemm_tma_kernel(const __grid_constant__ CUtensorMap wmap,
                     const __grid_constant__ CUtensorMap amap,
                     float* __restrict__ Cpart,
                     int N, int kChunk, int zW, int zA, int batched,
                     long cBatchStride)
{
    extern __shared__ __align__(128) unsigned char smem[];
    const uint32_t smemB = smem_u32(smem);

    const int tid  = threadIdx.x;
    const int wid  = tid >> 5;
    const int lane = tid & 31;
    const int j0    = blockIdx.x * TM;
    const int kBase = blockIdx.y * kChunk;
    const int nChunks = kChunk >> 5;

    const int zw = batched ? blockIdx.z : zW;
    const int za = batched ? blockIdx.z : zA;
    if (batched) Cpart += (long)blockIdx.z * cBatchStride;
    Cpart += (long)blockIdx.y * (long)N * B_;

    if (tid == 0) {
#pragma unroll
        for (int i = 0; i < 4; i++) {
            MBAR_INIT(smemB + SM_MBAR  + i * 8, 1);   // full: producer arrive+tx
            MBAR_INIT(smemB + SM_MBARE + i * 8, 8);   // empty: one arrive per warp
        }
    }
    __syncthreads();

    // ---- producer: one 16KB W box + one 8KB Act box per stage ----
    auto issue = [&](int c) {
        const int st = c & 3;
        const uint32_t mb = smemB + SM_MBAR + st * 8;
        MBAR_EXPECT(mb, 24576u);
        const uint32_t sb = smemB + (uint32_t)st * STAGE_SZ;
        TMA3D(sb,         &wmap, kBase + c * KC, j0, zw, mb);
        TMA3D(sb + 16384, &amap, kBase + c * KC, 0,  za, mb);
    };

    if (tid == 0) {
        for (int p = 0; p < 3 && p < nChunks; p++) issue(p);
    }

    // ---- mma mapping: 8 warps = 4(M) x 2(N); warp tile 32x32 ----
    const int wm = wid & 3, wn = wid >> 2;
    const int r7 = lane & 7;
    const int aKhi = lane >> 4;
    const int bKhi = (lane >> 3) & 1;
    const int bNoff = (lane & 7) + ((lane >> 4) << 3);
    const uint32_t aOff0 = (uint32_t)(wm * 32 + (lane & 15)) * 128;
    const uint32_t aOff1 = aOff0 + 2048;
    const uint32_t bOff0 = 16384 + (uint32_t)(wn * 32 + bNoff) * 128;
    const uint32_t bOff1 = bOff0 + 2048;

    float acc[2][4][4];
#pragma unroll
    for (int mt = 0; mt < 2; mt++)
#pragma unroll
        for (int nt = 0; nt < 4; nt++)
#pragma unroll
            for (int q = 0; q < 4; q++) acc[mt][nt][q] = 0.0f;

    for (int c = 0; c < nChunks; ++c) {
        // producer refill: wait until all warps released stage, then issue
        if (tid == 0 && c + 3 < nChunks) {
            const int X = c + 3;
            mbar_wait(smemB + SM_MBARE + (X & 3) * 8, (uint32_t)((X >> 2) + 1) & 1);
            issue(X);
        }

        mbar_wait(smemB + SM_MBAR + (c & 3) * 8, (uint32_t)(c >> 2) & 1);

        // ---- MMA on stage c&3: 4 k8 steps ----
        const uint32_t sb = smemB + (uint32_t)(c & 3) * STAGE_SZ;
#pragma unroll
        for (int s = 0; s < 4; s++) {
            uint32_t aF[2][4], bF[2][4];
            const uint32_t ga = (uint32_t)(((2 * s + aKhi) ^ r7) << 4);
            LDM_X4(aF[0], sb + aOff0 + ga);
            LDM_X4(aF[1], sb + aOff1 + ga);
            const uint32_t gb = (uint32_t)(((2 * s + bKhi) ^ r7) << 4);
            LDM_X4(bF[0], sb + bOff0 + gb);
            LDM_X4(bF[1], sb + bOff1 + gb);
#pragma unroll
            for (int mt = 0; mt < 2; mt++)
#pragma unroll
                for (int q = 0; q < 4; q++) aF[mt][q] = to_tf32_u(aF[mt][q]);
#pragma unroll
            for (int pr = 0; pr < 2; pr++)
#pragma unroll
                for (int q = 0; q < 4; q++) bF[pr][q] = to_tf32_u(bF[pr][q]);
#pragma unroll
            for (int mt = 0; mt < 2; mt++)
#pragma unroll
                for (int nt = 0; nt < 4; nt++) {
                    const int pr = nt >> 1, hf = (nt & 1) * 2;
                    MMA_TF32(acc[mt][nt], aF[mt], bF[pr][hf], bF[pr][hf + 1]);
                }
        }

        // release stage: one arrive per warp (reads done — LDSM results in regs)
        __syncwarp();
        if (lane == 0) MBAR_ARRIVE(smemB + SM_MBARE + (c & 3) * 8);
    }

    // ---- epilogue: write partial sums, layout [j][b] ----
#pragma unroll
    for (int mt = 0; mt < 2; mt++)
#pragma unroll
        for (int nt = 0; nt < 4; nt++) {
            const int j = j0 + wm * 32 + mt * 16 + (lane >> 2);
            const int b = wn * 32 + nt * 8 + (lane & 3) * 2;
            *reinterpret_cast<float2*>(&Cpart[(long)j * B_ + b]) =
                make_float2(acc[mt][nt][0], acc[mt][nt][1]);
            *reinterpret_cast<float2*>(&Cpart[(long)(j + 8) * B_ + b]) =
                make_float2(acc[mt][nt][2], acc[mt][nt][3]);
        }
}

// ---------------------------------------------------------------------------
// out[b][j] = bias[j] + sum_p parts[p][j][b]   (transposing combine)
// ---------------------------------------------------------------------------
__global__ void combine_t_kernel(const float* __restrict__ parts, int nsplit,
                                 const float* __restrict__ bias,
                                 float* __restrict__ out, int N)
{
    int idx = blockIdx.x * 256 + threadIdx.x;
    if (idx >= N * B_) return;
    int j = idx >> 6;
    int b = idx & 63;
    float s = bias[j];
    for (int p = 0; p < nsplit; p++) s += parts[(long)p * N * B_ + idx];
    out[(long)b * N + j] = s;
}

// ---------------------------------------------------------------------------
// GRU gate fusion; gi/gh partials in [p][j(4608)][b] layout.
// ---------------------------------------------------------------------------
__global__ void gru_gate_kernel(const float* __restrict__ giParts,
                                const float* __restrict__ ghParts,
                                const float* __restrict__ b_ih,
                                const float* __restrict__ b_hh,
                                const float* __restrict__ h_prev,   // [b][h]
                                float* __restrict__ h_out)          // [b][h]
{
    int idx = blockIdx.x * 256 + threadIdx.x;
    if (idx >= B_ * H_) return;
    int j = idx >> 6;
    int b = idx & 63;

    float gir = b_ih[j], giz = b_ih[H_ + j], gin = b_ih[2 * H_ + j];
#pragma unroll
    for (int p = 0; p < GI_SPLIT; p++) {
        const float* P = giParts + (long)p * H3_ * B_;
        gir += P[(long)j * B_ + b];
        giz += P[(long)(H_ + j) * B_ + b];
        gin += P[(long)(2 * H_ + j) * B_ + b];
    }
    float ghr = b_hh[j], ghz = b_hh[H_ + j], ghn = b_hh[2 * H_ + j];
#pragma unroll
    for (int p = 0; p < GH_SPLIT; p++) {
        const float* P = ghParts + (long)p * H3_ * B_;
        ghr += P[(long)j * B_ + b];
        ghz += P[(long)(H_ + j) * B_ + b];
        ghn += P[(long)(2 * H_ + j) * B_ + b];
    }

    float r = 1.0f / (1.0f + expf(-(gir + ghr)));
    float z = 1.0f / (1.0f + expf(-(giz + ghz)));
    float n = tanhf(gin + r * ghn);
    float hp = h_prev[(long)b * H_ + j];
    h_out[(long)b * H_ + j] = (1.0f - z) * n + z * hp;
}

// ---------------------------------------------------------------------------
// Host-side tensormap encoding via runtime driver-entry-point (no -lcuda).
// ---------------------------------------------------------------------------
typedef CUresult (*PFN_encodeTiled)(
    CUtensorMap*, CUtensorMapDataType, unsigned int, void*,
    const unsigned long long*, const unsigned long long*,
    const unsigned int*, const unsigned int*,
    CUtensorMapInterleave, CUtensorMapSwizzle,
    CUtensorMapL2promotion, CUtensorMapFloatOOBfill);

static PFN_encodeTiled get_encoder() {
    void* fp = nullptr;
    cudaDriverEntryPointQueryResult st;
    cudaGetDriverEntryPointByVersion("cuTensorMapEncodeTiled", &fp, 12000,
                                     cudaEnableDefault, &st);
    return (PFN_encodeTiled)fp;
}

static void enc3d(PFN_encodeTiled f, CUtensorMap* m, const void* base,
                  unsigned long long d0, unsigned long long d1,
                  unsigned long long d2, unsigned int boxN)
{
    unsigned long long dims[3]    = {d0, d1, d2};
    unsigned long long strides[2] = {d0 * 4ull, d0 * 4ull * d1};
    unsigned int box[3] = {32u, boxN, 1u};
    unsigned int es[3]  = {1u, 1u, 1u};
    f(m, CU_TENSOR_MAP_DATA_TYPE_FLOAT32, 3, const_cast<void*>(base),
      dims, strides, box, es,
      CU_TENSOR_MAP_INTERLEAVE_NONE, CU_TENSOR_MAP_SWIZZLE_128B,
      CU_TENSOR_MAP_L2_PROMOTION_L2_128B, CU_TENSOR_MAP_FLOAT_OOB_FILL_NONE);
}

// ---------------------------------------------------------------------------
extern "C" void kernel_launch(void* const* d_in, const int* in_sizes, int n_in,
                              void* d_out, int out_size)
{
    const float* x      = (const float*)d_in[0];   // [64,320]
    const float* hidden = (const float*)d_in[1];   // [3,64,1536]
    const float* w_i2h  = (const float*)d_in[2];   // [1536,320]
    const float* b_i2h  = (const float*)d_in[3];   // [1536]
    const float* w_ih   = (const float*)d_in[4];   // [3,4608,1536]
    const float* w_hh   = (const float*)d_in[5];   // [3,4608,1536]
    const float* b_ih   = (const float*)d_in[6];   // [3,4608]
    const float* b_hh   = (const float*)d_in[7];   // [3,4608]
    const float* w_h2o  = (const float*)d_in[8];   // [256,1536]
    const float* b_h2o  = (const float*)d_in[9];   // [256]
    (void)in_sizes; (void)n_in; (void)out_size;

    float* out     = (float*)d_out;                // [64,256]
    float* hid_out = (float*)d_out + B_ * O_;      // [3,64,1536]

    float *gh_ptr, *gi_ptr, *inp_ptr, *outp_ptr;
    cudaGetSymbolAddress((void**)&gh_ptr,   g_gh);
    cudaGetSymbolAddress((void**)&gi_ptr,   g_gi_part);
    cudaGetSymbolAddress((void**)&inp_ptr,  g_inp);
    cudaGetSymbolAddress((void**)&outp_ptr, g_out_part);

    cudaFuncSetAttribute(gemm_tma_kernel, cudaFuncAttributeMaxDynamicSharedMemorySize, SM_TOTAL);

    // lazily created side stream + events (first call is the non-captured
    // correctness run; during capture only launches/event ops are enqueued)
    static cudaStream_t sideS = nullptr;
    static cudaEvent_t evFork = nullptr, evGh[3] = {nullptr, nullptr, nullptr};
    if (!sideS) {
        cudaStreamCreateWithFlags(&sideS, cudaStreamNonBlocking);
        cudaEventCreateWithFlags(&evFork, cudaEventDisableTiming);
        for (int l = 0; l < 3; l++)
            cudaEventCreateWithFlags(&evGh[l], cudaEventDisableTiming);
    }

    PFN_encodeTiled f = get_encoder();
    static CUtensorMap mWhh, mHid, mWih, mWi2h, mX, mWh2o, mInp, mHidO;
    enc3d(f, &mWhh,  w_hh,    H_, H3_, L_, 128);   // (k, j, layer)
    enc3d(f, &mHid,  hidden,  H_, B_,  L_, 64);
    enc3d(f, &mWih,  w_ih,    H_, H3_, L_, 128);
    enc3d(f, &mWi2h, w_i2h,   I_, H_,  1,  128);
    enc3d(f, &mX,    x,       I_, B_,  1,  64);
    enc3d(f, &mWh2o, w_h2o,   H_, O_,  1,  128);
    enc3d(f, &mInp,  inp_ptr, H_, B_,  1,  64);
    enc3d(f, &mHidO, hid_out, H_, B_,  L_, 64);

    const long hLayerStride = (long)B_ * H_;
    const long ghLayerStride = (long)GH_SPLIT * H3_ * B_;

    // ---- fork: gh per layer on side stream (independent of main chain) ----
    cudaEventRecord(evFork, 0);
    cudaStreamWaitEvent(sideS, evFork, 0);
    for (int l = 0; l < L_; l++) {
        gemm_tma_kernel<<<dim3(H3_ / TM, GH_SPLIT, 1), 256, SM_TOTAL, sideS>>>(
            mWhh, mHid, gh_ptr + (long)l * ghLayerStride,
            H3_, H_ / GH_SPLIT, l, l, 0, 0);
        cudaEventRecord(evGh[l], sideS);
    }

    // ---- main stream: i2h -> chain ----
    gemm_tma_kernel<<<dim3(H_ / TM, I2H_SPLIT, 1), 256, SM_TOTAL>>>(
        mWi2h, mX, gi_ptr, H_, I_ / I2H_SPLIT, 0, 0, 0, 0);
    combine_t_kernel<<<(H_ * B_ + 255) / 256, 256>>>(gi_ptr, I2H_SPLIT, b_i2h, inp_ptr, H_);

    for (int l = 0; l < L_; l++) {
        const int zA = (l == 0) ? 0 : (l - 1);
        gemm_tma_kernel<<<dim3(H3_ / TM, GI_SPLIT, 1), 256, SM_TOTAL>>>(
            mWih, (l == 0) ? mInp : mHidO, gi_ptr,
            H3_, H_ / GI_SPLIT, l, zA, 0, 0);
        cudaStreamWaitEvent(0, evGh[l], 0);   // join gh[l] before gate
        gru_gate_kernel<<<(B_ * H_ + 255) / 256, 256>>>(
            gi_ptr, gh_ptr + (long)l * ghLayerStride,
            b_ih + (long)l * H3_, b_hh + (long)l * H3_,
            hidden + (long)l * hLayerStride,
            hid_out + (long)l * hLayerStride);
    }

    // ---- h2o ----
    gemm_tma_kernel<<<dim3(O_ / TM, H2O_SPLIT, 1), 256, SM_TOTAL>>>(
        mWh2o, mHidO, outp_ptr, O_, H_ / H2O_SPLIT, 0, 2, 0, 0);
    combine_t_kernel<<<(O_ * B_ + 255) / 256, 256>>>(outp_ptr, H2O_SPLIT, b_h2o, out, O_);
}

// round 15
// speedup vs baseline: 2.0645x; 1.0004x over previous
#include <cuda_runtime.h>
#include <cuda.h>
#include <cuda_bf16.h>
#include <math.h>
#include <stdint.h>

// Problem constants
#define B_  64
#define I_  320
#define H_  1536
#define L_  3
#define O_  256
#define H3_ 4608

#define GH_SPLIT 4
#define GI_SPLIT 8
#define I2H_SPLIT 5
#define H2O_SPLIT 24

#define KC 32            // fp32 k per chunk (128B row; TMA box [32, rows])
#define TM 128           // weight rows per block (MMA M side)
#define STAGE_SZ 24576   // W 128x128B (16KB) + Act 64x128B (8KB)
#define NSTAGE 3
#define SM_MBAR  73728   // 3 full barriers (8B each)
#define SM_MBARE 73760   // 3 empty barriers
#define SM_TOTAL 73792   // fits 3 CTAs/SM (3 x 73.8KB = 221KB <= 227KB)

// Device scratch (static, no allocation)
__device__ __align__(16) float g_gh[GH_SPLIT * L_ * H3_ * B_];   // [l][p][j][b]
__device__ __align__(16) float g_gi_part[GI_SPLIT * H3_ * B_];   // [p][j][b]
__device__ __align__(16) float g_inp[B_ * H_];                   // [b][h]
__device__ __align__(16) float g_out_part[H2O_SPLIT * O_ * B_];  // [p][o][b]

__device__ __forceinline__ uint32_t smem_u32(const void* p) {
    uint32_t a;
    asm("{ .reg .u64 t; cvta.to.shared.u64 t, %1; cvt.u32.u64 %0, t; }" : "=r"(a) : "l"(p));
    return a;
}

#define TMA3D(smemaddr, mapptr, x, y, z, mb)                                      \
    asm volatile("cp.async.bulk.tensor.3d.shared::cta.global.tile"                \
                 ".mbarrier::complete_tx::bytes [%0], [%1, {%2, %3, %4}], [%5];"  \
                 :: "r"(smemaddr), "l"(mapptr), "r"(x), "r"(y), "r"(z), "r"(mb)   \
                 : "memory")

#define MBAR_INIT(mb, cnt) \
    asm volatile("mbarrier.init.shared.b64 [%0], %1;" :: "r"(mb), "r"(cnt) : "memory")
#define MBAR_EXPECT(mb, bytes) \
    asm volatile("mbarrier.arrive.expect_tx.shared.b64 _, [%0], %1;" :: "r"(mb), "r"(bytes) : "memory")
#define MBAR_ARRIVE(mb) \
    asm volatile("mbarrier.arrive.release.cta.shared::cta.b64 _, [%0];" :: "r"(mb) : "memory")

__device__ __forceinline__ void mbar_wait(uint32_t mb, uint32_t parity) {
    asm volatile(
        "{\n\t.reg .pred P;\n\t"
        "WL_%=:\n\t"
        "mbarrier.try_wait.parity.acquire.cta.shared::cta.b64 P, [%0], %1, 0x989680;\n\t"
        "@P bra.uni WD_%=;\n\t"
        "bra.uni WL_%=;\n\t"
        "WD_%=:\n\t}"
        :: "r"(mb), "r"(parity) : "memory");
}

#define LDM_X4(r, addr)                                                          \
    asm volatile("ldmatrix.sync.aligned.m8n8.x4.shared.b16 {%0,%1,%2,%3}, [%4];" \
                 : "=r"((r)[0]), "=r"((r)[1]), "=r"((r)[2]), "=r"((r)[3])        \
                 : "r"(addr))

#define MMA_TF32(c, a, b0, b1)                                                   \
    asm volatile("mma.sync.aligned.m16n8k8.row.col.f32.tf32.tf32.f32 "           \
                 "{%0,%1,%2,%3}, {%4,%5,%6,%7}, {%8,%9}, {%0,%1,%2,%3};"         \
                 : "+f"((c)[0]), "+f"((c)[1]), "+f"((c)[2]), "+f"((c)[3])        \
                 : "r"((a)[0]), "r"((a)[1]), "r"((a)[2]), "r"((a)[3]),           \
                   "r"(b0), "r"(b1))

__device__ __forceinline__ uint32_t to_tf32_u(uint32_t x) {
    uint32_t y;
    asm("cvt.rna.tf32.f32 %0, %1;" : "=r"(y) : "f"(__uint_as_float(x)));
    return y;
}

// ---------------------------------------------------------------------------
// TMA-fed tf32 GEMM: Cpart[(z)][y][j][b] = sum_k W[j][k] * Act[b][k]
// 3-stage full/empty mbarrier pipeline, 3 CTAs/SM.
// Block tile 128(j) x 64(b); 8 warps of 32x32.
// ---------------------------------------------------------------------------
__global__ __launch_bounds__(256, 3)
void gemm_tma_kernel(const __grid_constant__ CUtensorMap wmap,
                     const __grid_constant__ CUtensorMap amap,
                     float* __restrict__ Cpart,
                     int N, int kChunk, int zW, int zA, int batched,
                     long cBatchStride)
{
    extern __shared__ __align__(128) unsigned char smem[];
    const uint32_t smemB = smem_u32(smem);

    const int tid  = threadIdx.x;
    const int wid  = tid >> 5;
    const int lane = tid & 31;
    const int j0    = blockIdx.x * TM;
    const int kBase = blockIdx.y * kChunk;
    const int nChunks = kChunk >> 5;

    const int zw = batched ? blockIdx.z : zW;
    const int za = batched ? blockIdx.z : zA;
    if (batched) Cpart += (long)blockIdx.z * cBatchStride;
    Cpart += (long)blockIdx.y * (long)N * B_;

    if (tid == 0) {
#pragma unroll
        for (int i = 0; i < NSTAGE; i++) {
            MBAR_INIT(smemB + SM_MBAR  + i * 8, 1);   // full: producer arrive+tx
            MBAR_INIT(smemB + SM_MBARE + i * 8, 8);   // empty: one arrive per warp
        }
    }
    __syncthreads();

    // ---- producer: one 16KB W box + one 8KB Act box per stage ----
    auto issue = [&](int c) {
        const int st = c % NSTAGE;
        const uint32_t mb = smemB + SM_MBAR + st * 8;
        MBAR_EXPECT(mb, 24576u);
        const uint32_t sb = smemB + (uint32_t)st * STAGE_SZ;
        TMA3D(sb,         &wmap, kBase + c * KC, j0, zw, mb);
        TMA3D(sb + 16384, &amap, kBase + c * KC, 0,  za, mb);
    };

    if (tid == 0) {
        for (int p = 0; p < 2 && p < nChunks; p++) issue(p);
    }

    // ---- mma mapping: 8 warps = 4(M) x 2(N); warp tile 32x32 ----
    const int wm = wid & 3, wn = wid >> 2;
    const int r7 = lane & 7;
    const int aKhi = lane >> 4;
    const int bKhi = (lane >> 3) & 1;
    const int bNoff = (lane & 7) + ((lane >> 4) << 3);
    const uint32_t aOff0 = (uint32_t)(wm * 32 + (lane & 15)) * 128;
    const uint32_t aOff1 = aOff0 + 2048;
    const uint32_t bOff0 = 16384 + (uint32_t)(wn * 32 + bNoff) * 128;
    const uint32_t bOff1 = bOff0 + 2048;

    float acc[2][4][4];
#pragma unroll
    for (int mt = 0; mt < 2; mt++)
#pragma unroll
        for (int nt = 0; nt < 4; nt++)
#pragma unroll
            for (int q = 0; q < 4; q++) acc[mt][nt][q] = 0.0f;

    for (int c = 0; c < nChunks; ++c) {
        // producer refill: wait until all warps released stage, then issue
        if (tid == 0 && c + 2 < nChunks) {
            const int X = c + 2;
            mbar_wait(smemB + SM_MBARE + (X % NSTAGE) * 8, (uint32_t)((X / NSTAGE) + 1) & 1);
            issue(X);
        }

        mbar_wait(smemB + SM_MBAR + (c % NSTAGE) * 8, (uint32_t)(c / NSTAGE) & 1);

        // ---- MMA on stage c%3: 4 k8 steps ----
        const uint32_t sb = smemB + (uint32_t)(c % NSTAGE) * STAGE_SZ;
#pragma unroll
        for (int s = 0; s < 4; s++) {
            uint32_t aF[2][4], bF[2][4];
            const uint32_t ga = (uint32_t)(((2 * s + aKhi) ^ r7) << 4);
            LDM_X4(aF[0], sb + aOff0 + ga);
            LDM_X4(aF[1], sb + aOff1 + ga);
            const uint32_t gb = (uint32_t)(((2 * s + bKhi) ^ r7) << 4);
            LDM_X4(bF[0], sb + bOff0 + gb);
            LDM_X4(bF[1], sb + bOff1 + gb);
#pragma unroll
            for (int mt = 0; mt < 2; mt++)
#pragma unroll
                for (int q = 0; q < 4; q++) aF[mt][q] = to_tf32_u(aF[mt][q]);
#pragma unroll
            for (int pr = 0; pr < 2; pr++)
#pragma unroll
                for (int q = 0; q < 4; q++) bF[pr][q] = to_tf32_u(bF[pr][q]);
#pragma unroll
            for (int mt = 0; mt < 2; mt++)
#pragma unroll
                for (int nt = 0; nt < 4; nt++) {
                    const int pr = nt >> 1, hf = (nt & 1) * 2;
                    MMA_TF32(acc[mt][nt], aF[mt], bF[pr][hf], bF[pr][hf + 1]);
                }
        }

        // release stage: one arrive per warp (reads done — LDSM results in regs)
        __syncwarp();
        if (lane == 0) MBAR_ARRIVE(smemB + SM_MBARE + (c % NSTAGE) * 8);
    }

    // ---- epilogue: write partial sums, layout [j][b] ----
#pragma unroll
    for (int mt = 0; mt < 2; mt++)
#pragma unroll
        for (int nt = 0; nt < 4; nt++) {
            const int j = j0 + wm * 32 + mt * 16 + (lane >> 2);
            const int b = wn * 32 + nt * 8 + (lane & 3) * 2;
            *reinterpret_cast<float2*>(&Cpart[(long)j * B_ + b]) =
                make_float2(acc[mt][nt][0], acc[mt][nt][1]);
            *reinterpret_cast<float2*>(&Cpart[(long)(j + 8) * B_ + b]) =
                make_float2(acc[mt][nt][2], acc[mt][nt][3]);
        }
}

// ---------------------------------------------------------------------------
// out[b][j] = bias[j] + sum_p parts[p][j][b]   (transposing combine)
// ---------------------------------------------------------------------------
__global__ void combine_t_kernel(const float* __restrict__ parts, int nsplit,
                                 const float* __restrict__ bias,
                                 float* __restrict__ out, int N)
{
    int idx = blockIdx.x * 256 + threadIdx.x;
    if (idx >= N * B_) return;
    int j = idx >> 6;
    int b = idx & 63;
    float s = bias[j];
    for (int p = 0; p < nsplit; p++) s += parts[(long)p * N * B_ + idx];
    out[(long)b * N + j] = s;
}

// ---------------------------------------------------------------------------
// GRU gate fusion; gi/gh partials in [p][j(4608)][b] layout.
// ---------------------------------------------------------------------------
__global__ void gru_gate_kernel(const float* __restrict__ giParts,
                                const float* __restrict__ ghParts,
                                const float* __restrict__ b_ih,
                                const float* __restrict__ b_hh,
                                const float* __restrict__ h_prev,   // [b][h]
                                float* __restrict__ h_out)          // [b][h]
{
    int idx = blockIdx.x * 256 + threadIdx.x;
    if (idx >= B_ * H_) return;
    int j = idx >> 6;
    int b = idx & 63;

    float gir = b_ih[j], giz = b_ih[H_ + j], gin = b_ih[2 * H_ + j];
#pragma unroll
    for (int p = 0; p < GI_SPLIT; p++) {
        const float* P = giParts + (long)p * H3_ * B_;
        gir += P[(long)j * B_ + b];
        giz += P[(long)(H_ + j) * B_ + b];
        gin += P[(long)(2 * H_ + j) * B_ + b];
    }
    float ghr = b_hh[j], ghz = b_hh[H_ + j], ghn = b_hh[2 * H_ + j];
#pragma unroll
    for (int p = 0; p < GH_SPLIT; p++) {
        const float* P = ghParts + (long)p * H3_ * B_;
        ghr += P[(long)j * B_ + b];
        ghz += P[(long)(H_ + j) * B_ + b];
        ghn += P[(long)(2 * H_ + j) * B_ + b];
    }

    float r = 1.0f / (1.0f + expf(-(gir + ghr)));
    float z = 1.0f / (1.0f + expf(-(giz + ghz)));
    float n = tanhf(gin + r * ghn);
    float hp = h_prev[(long)b * H_ + j];
    h_out[(long)b * H_ + j] = (1.0f - z) * n + z * hp;
}

// ---------------------------------------------------------------------------
// Host-side tensormap encoding via runtime driver-entry-point (no -lcuda).
// ---------------------------------------------------------------------------
typedef CUresult (*PFN_encodeTiled)(
    CUtensorMap*, CUtensorMapDataType, unsigned int, void*,
    const unsigned long long*, const unsigned long long*,
    const unsigned int*, const unsigned int*,
    CUtensorMapInterleave, CUtensorMapSwizzle,
    CUtensorMapL2promotion, CUtensorMapFloatOOBfill);

static PFN_encodeTiled get_encoder() {
    void* fp = nullptr;
    cudaDriverEntryPointQueryResult st;
    cudaGetDriverEntryPointByVersion("cuTensorMapEncodeTiled", &fp, 12000,
                                     cudaEnableDefault, &st);
    return (PFN_encodeTiled)fp;
}

static void enc3d(PFN_encodeTiled f, CUtensorMap* m, const void* base,
                  unsigned long long d0, unsigned long long d1,
                  unsigned long long d2, unsigned int boxN)
{
    unsigned long long dims[3]    = {d0, d1, d2};
    unsigned long long strides[2] = {d0 * 4ull, d0 * 4ull * d1};
    unsigned int box[3] = {32u, boxN, 1u};
    unsigned int es[3]  = {1u, 1u, 1u};
    f(m, CU_TENSOR_MAP_DATA_TYPE_FLOAT32, 3, const_cast<void*>(base),
      dims, strides, box, es,
      CU_TENSOR_MAP_INTERLEAVE_NONE, CU_TENSOR_MAP_SWIZZLE_128B,
      CU_TENSOR_MAP_L2_PROMOTION_L2_128B, CU_TENSOR_MAP_FLOAT_OOB_FILL_NONE);
}

// ---------------------------------------------------------------------------
extern "C" void kernel_launch(void* const* d_in, const int* in_sizes, int n_in,
                              void* d_out, int out_size)
{
    const float* x      = (const float*)d_in[0];   // [64,320]
    const float* hidden = (const float*)d_in[1];   // [3,64,1536]
    const float* w_i2h  = (const float*)d_in[2];   // [1536,320]
    const float* b_i2h  = (const float*)d_in[3];   // [1536]
    const float* w_ih   = (const float*)d_in[4];   // [3,4608,1536]
    const float* w_hh   = (const float*)d_in[5];   // [3,4608,1536]
    const float* b_ih   = (const float*)d_in[6];   // [3,4608]
    const float* b_hh   = (const float*)d_in[7];   // [3,4608]
    const float* w_h2o  = (const float*)d_in[8];   // [256,1536]
    const float* b_h2o  = (const float*)d_in[9];   // [256]
    (void)in_sizes; (void)n_in; (void)out_size;

    float* out     = (float*)d_out;                // [64,256]
    float* hid_out = (float*)d_out + B_ * O_;      // [3,64,1536]

    float *gh_ptr, *gi_ptr, *inp_ptr, *outp_ptr;
    cudaGetSymbolAddress((void**)&gh_ptr,   g_gh);
    cudaGetSymbolAddress((void**)&gi_ptr,   g_gi_part);
    cudaGetSymbolAddress((void**)&inp_ptr,  g_inp);
    cudaGetSymbolAddress((void**)&outp_ptr, g_out_part);

    cudaFuncSetAttribute(gemm_tma_kernel, cudaFuncAttributeMaxDynamicSharedMemorySize, SM_TOTAL);

    // lazily created side stream + events (first call is the non-captured
    // correctness run; during capture only launches/event ops are enqueued)
    static cudaStream_t sideS = nullptr;
    static cudaEvent_t evFork = nullptr, evGh[3] = {nullptr, nullptr, nullptr};
    if (!sideS) {
        cudaStreamCreateWithFlags(&sideS, cudaStreamNonBlocking);
        cudaEventCreateWithFlags(&evFork, cudaEventDisableTiming);
        for (int l = 0; l < 3; l++)
            cudaEventCreateWithFlags(&evGh[l], cudaEventDisableTiming);
    }

    PFN_encodeTiled f = get_encoder();
    static CUtensorMap mWhh, mHid, mWih, mWi2h, mX, mWh2o, mInp, mHidO;
    enc3d(f, &mWhh,  w_hh,    H_, H3_, L_, 128);   // (k, j, layer)
    enc3d(f, &mHid,  hidden,  H_, B_,  L_, 64);
    enc3d(f, &mWih,  w_ih,    H_, H3_, L_, 128);
    enc3d(f, &mWi2h, w_i2h,   I_, H_,  1,  128);
    enc3d(f, &mX,    x,       I_, B_,  1,  64);
    enc3d(f, &mWh2o, w_h2o,   H_, O_,  1,  128);
    enc3d(f, &mInp,  inp_ptr, H_, B_,  1,  64);
    enc3d(f, &mHidO, hid_out, H_, B_,  L_, 64);

    const long hLayerStride = (long)B_ * H_;
    const long ghLayerStride = (long)GH_SPLIT * H3_ * B_;

    // ---- fork: gh per layer on side stream (independent of main chain) ----
    cudaEventRecord(evFork, 0);
    cudaStreamWaitEvent(sideS, evFork, 0);
    for (int l = 0; l < L_; l++) {
        gemm_tma_kernel<<<dim3(H3_ / TM, GH_SPLIT, 1), 256, SM_TOTAL, sideS>>>(
            mWhh, mHid, gh_ptr + (long)l * ghLayerStride,
            H3_, H_ / GH_SPLIT, l, l, 0, 0);
        cudaEventRecord(evGh[l], sideS);
    }

    // ---- main stream: i2h -> chain ----
    gemm_tma_kernel<<<dim3(H_ / TM, I2H_SPLIT, 1), 256, SM_TOTAL>>>(
        mWi2h, mX, gi_ptr, H_, I_ / I2H_SPLIT, 0, 0, 0, 0);
    combine_t_kernel<<<(H_ * B_ + 255) / 256, 256>>>(gi_ptr, I2H_SPLIT, b_i2h, inp_ptr, H_);

    for (int l = 0; l < L_; l++) {
        const int zA = (l == 0) ? 0 : (l - 1);
        gemm_tma_kernel<<<dim3(H3_ / TM, GI_SPLIT, 1), 256, SM_TOTAL>>>(
            mWih, (l == 0) ? mInp : mHidO, gi_ptr,
            H3_, H_ / GI_SPLIT, l, zA, 0, 0);
        cudaStreamWaitEvent(0, evGh[l], 0);   // join gh[l] before gate
        gru_gate_kernel<<<(B_ * H_ + 255) / 256, 256>>>(
            gi_ptr, gh_ptr + (long)l * ghLayerStride,
            b_ih + (long)l * H3_, b_hh + (long)l * H3_,
            hidden + (long)l * hLayerStride,
            hid_out + (long)l * hLayerStride);
    }

    // ---- h2o ----
    gemm_tma_kernel<<<dim3(O_ / TM, H2O_SPLIT, 1), 256, SM_TOTAL>>>(
        mWh2o, mHidO, outp_ptr, O_, H_ / H2O_SPLIT, 0, 2, 0, 0);
    combine_t_kernel<<<(O_ * B_ + 255) / 256, 256>>>(outp_ptr, H2O_SPLIT, b_h2o, out, O_);
}